// round 5
// baseline (speedup 1.0000x reference)
#include <cuda_runtime.h>
#include <cuda_bf16.h>
#include <cstdint>
#include <cstddef>

#define TT   100
#define BB   1024
#define NHD  128
#define NGATE 512
#define NIC  268
#define NBOT 256
#define NPC  256
#define NHDC 12
#define TB   (TT * BB)

// device scratch
__device__ float g_h0[BB * NHD];
__device__ float g_c0[BB * NHD];
__device__ __nv_bfloat16 g_hh[(size_t)TB * NHD];   // h_t split hi
__device__ __nv_bfloat16 g_hl[(size_t)TB * NHD];   // h_t split lo
__device__ __nv_bfloat16 g_bnh[(size_t)TB * NBOT];
__device__ __nv_bfloat16 g_bnl[(size_t)TB * NBOT];

__device__ __forceinline__ float sigm(float v) { return 1.0f / (1.0f + __expf(-v)); }
__device__ __forceinline__ void split2(float v, __nv_bfloat16& hi, __nv_bfloat16& lo) {
    hi = __float2bfloat16(v);
    lo = __float2bfloat16(v - __bfloat162float(hi));
}
__device__ __forceinline__ uint32_t smem_u32(const void* p) {
    uint32_t a;
    asm("{ .reg .u64 t; cvta.to.shared.u64 t, %1; cvt.u32.u64 %0, t; }" : "=r"(a) : "l"(p));
    return a;
}
__device__ __forceinline__ void ldsm_x4(uint32_t& r0, uint32_t& r1, uint32_t& r2,
                                        uint32_t& r3, uint32_t addr) {
    asm volatile("ldmatrix.sync.aligned.m8n8.x4.shared.b16 {%0,%1,%2,%3}, [%4];"
                 : "=r"(r0), "=r"(r1), "=r"(r2), "=r"(r3) : "r"(addr));
}
__device__ __forceinline__ void ldsm_x4_t(uint32_t& r0, uint32_t& r1, uint32_t& r2,
                                          uint32_t& r3, uint32_t addr) {
    asm volatile("ldmatrix.sync.aligned.m8n8.x4.trans.shared.b16 {%0,%1,%2,%3}, [%4];"
                 : "=r"(r0), "=r"(r1), "=r"(r2), "=r"(r3) : "r"(addr));
}
__device__ __forceinline__ void mma16816(float* d, const uint32_t* a, const uint32_t* b) {
    asm volatile(
        "mma.sync.aligned.m16n8k16.row.col.f32.bf16.bf16.f32 "
        "{%0,%1,%2,%3}, {%4,%5,%6,%7}, {%8,%9}, {%0,%1,%2,%3};"
        : "+f"(d[0]), "+f"(d[1]), "+f"(d[2]), "+f"(d[3])
        : "r"(a[0]), "r"(a[1]), "r"(a[2]), "r"(a[3]), "r"(b[0]), "r"(b[1]));
}
#define CLUSTER_SYNC() do { \
    asm volatile("barrier.cluster.arrive.aligned;" ::: "memory"); \
    asm volatile("barrier.cluster.wait.aligned;" ::: "memory"); \
} while (0)

// ---------------------------------------------------------------------------
// fp32 GEMM for h0/c0 init
// ---------------------------------------------------------------------------
__global__ void gemm_kernel(const float* __restrict__ A, const float* __restrict__ W,
                            const float* __restrict__ bias, float* __restrict__ C,
                            int M, int N, int K)
{
    __shared__ float As[16][68];
    __shared__ float Ws[16][68];
    const int tid = threadIdx.x;
    const int tx = tid & 15, ty = tid >> 4;
    const int n0 = blockIdx.x * 64, m0 = blockIdx.y * 64;

    float acc[4][4];
#pragma unroll
    for (int r = 0; r < 4; r++)
#pragma unroll
        for (int q = 0; q < 4; q++) acc[r][q] = 0.0f;

    for (int k0 = 0; k0 < K; k0 += 16) {
        {
            const int k = tid & 15, m = tid >> 4;
#pragma unroll
            for (int p = 0; p < 4; p++) {
                const int mm = m + p * 16;
                float v = 0.0f;
                if (k0 + k < K) v = A[(size_t)(m0 + mm) * K + (k0 + k)];
                As[k][mm] = v;
            }
        }
        {
            const int n = tid & 63, kb = tid >> 6;
#pragma unroll
            for (int p = 0; p < 4; p++) {
                const int kk = kb + p * 4;
                float v = 0.0f;
                if ((k0 + kk < K) && (n0 + n < N)) v = W[(size_t)(k0 + kk) * N + (n0 + n)];
                Ws[kk][n] = v;
            }
        }
        __syncthreads();
#pragma unroll
        for (int kk = 0; kk < 16; kk++) {
            const float4 a4 = *(const float4*)&As[kk][ty * 4];
            const float4 b4 = *(const float4*)&Ws[kk][tx * 4];
            const float av[4] = {a4.x, a4.y, a4.z, a4.w};
            const float bv[4] = {b4.x, b4.y, b4.z, b4.w};
#pragma unroll
            for (int r = 0; r < 4; r++)
#pragma unroll
                for (int q = 0; q < 4; q++)
                    acc[r][q] = fmaf(av[r], bv[q], acc[r][q]);
        }
        __syncthreads();
    }
#pragma unroll
    for (int r = 0; r < 4; r++) {
        const int m = m0 + ty * 4 + r;
#pragma unroll
        for (int q = 0; q < 4; q++) {
            const int n = n0 + tx * 4 + q;
            if (n < N) C[(size_t)m * N + n] = acc[r][q] + (bias ? bias[n] : 0.0f);
        }
    }
}

// ---------------------------------------------------------------------------
// LSTM recurrence: 128 blocks (16 clusters x 8), 512 threads, cluster barrier.
// Block owns 64 rows x 16 units (gate-interleaved cols c = u*4+q).
// ---------------------------------------------------------------------------
#define LSTM_SMEM ((128 * 64 + 64 * 128 + 3 * 64 + 64 + 64 * 4) * 4)

__global__ void __launch_bounds__(512, 1) __cluster_dims__(8, 1, 1)
lstm_kernel(const float* __restrict__ x, const float* __restrict__ rnn_w,
            const float* __restrict__ rnn_b,
            float* __restrict__ hs, float* __restrict__ cs)
{
    extern __shared__ float sm[];
    float* wh_s = sm;              // [128][64]
    float* h_s  = sm + 8192;       // [64][128]
    float* wx_s = h_s + 8192;      // [3][64]
    float* b_s  = wx_s + 192;      // [64]
    float* x_s  = b_s + 64;        // [64][4]

    const int tid = threadIdx.x;
    const int tx = tid & 15, ty = tid >> 4;
    const int cg = blockIdx.x & 7;
    const int r0 = (blockIdx.x >> 3) * 64;
    const int hu0 = cg * 16;

    for (int idx = tid; idx < 128 * 64; idx += 512) {
        const int k = idx >> 6, c = idx & 63;
        const int u = c >> 2, q = c & 3;
        wh_s[idx] = rnn_w[(size_t)(3 + k) * NGATE + q * NHD + hu0 + u];
    }
    if (tid < 192) {
        const int m = tid >> 6, c = tid & 63;
        const int u = c >> 2, q = c & 3;
        wx_s[m * 64 + c] = rnn_w[(size_t)m * NGATE + q * NHD + hu0 + u];
    }
    if (tid < 64) {
        const int u = tid >> 2, q = tid & 3;
        b_s[tid] = rnn_b[q * NHD + hu0 + u];
    }

    float creg[2];
#pragma unroll
    for (int r = 0; r < 2; r++)
        creg[r] = g_c0[(size_t)(r0 + ty * 2 + r) * NHD + hu0 + tx];

    const float* hprev = g_h0;

    for (int t = 0; t < TT; t++) {
        for (int i = tid; i < 64 * 32; i += 512) {
            const int row = i >> 5, c4 = i & 31;
            *(float4*)&h_s[row * 128 + c4 * 4] =
                *(const float4*)&hprev[(size_t)(r0 + row) * NHD + c4 * 4];
        }
        if (tid < 64) {
            const float* xp = x + ((size_t)t * BB + r0 + tid) * 3;
            x_s[tid * 4 + 0] = xp[0];
            x_s[tid * 4 + 1] = xp[1];
            x_s[tid * 4 + 2] = xp[2];
        }
        __syncthreads();

        float acc[2][4];
#pragma unroll
        for (int r = 0; r < 2; r++) {
            const float x0 = x_s[(ty * 2 + r) * 4 + 0];
            const float x1 = x_s[(ty * 2 + r) * 4 + 1];
            const float x2 = x_s[(ty * 2 + r) * 4 + 2];
#pragma unroll
            for (int q = 0; q < 4; q++) {
                const int c = tx * 4 + q;
                float v = b_s[c];
                v = fmaf(x0, wx_s[c], v);
                v = fmaf(x1, wx_s[64 + c], v);
                v = fmaf(x2, wx_s[128 + c], v);
                acc[r][q] = v;
            }
        }

#pragma unroll 4
        for (int k = 0; k < 128; k += 4) {
            const float4 w0 = *(const float4*)&wh_s[(k + 0) * 64 + tx * 4];
            const float4 w1 = *(const float4*)&wh_s[(k + 1) * 64 + tx * 4];
            const float4 w2 = *(const float4*)&wh_s[(k + 2) * 64 + tx * 4];
            const float4 w3 = *(const float4*)&wh_s[(k + 3) * 64 + tx * 4];
#pragma unroll
            for (int r = 0; r < 2; r++) {
                const float4 hv = *(const float4*)&h_s[(ty * 2 + r) * 128 + k];
                acc[r][0] = fmaf(hv.x, w0.x, acc[r][0]);
                acc[r][1] = fmaf(hv.x, w0.y, acc[r][1]);
                acc[r][2] = fmaf(hv.x, w0.z, acc[r][2]);
                acc[r][3] = fmaf(hv.x, w0.w, acc[r][3]);
                acc[r][0] = fmaf(hv.y, w1.x, acc[r][0]);
                acc[r][1] = fmaf(hv.y, w1.y, acc[r][1]);
                acc[r][2] = fmaf(hv.y, w1.z, acc[r][2]);
                acc[r][3] = fmaf(hv.y, w1.w, acc[r][3]);
                acc[r][0] = fmaf(hv.z, w2.x, acc[r][0]);
                acc[r][1] = fmaf(hv.z, w2.y, acc[r][1]);
                acc[r][2] = fmaf(hv.z, w2.z, acc[r][2]);
                acc[r][3] = fmaf(hv.z, w2.w, acc[r][3]);
                acc[r][0] = fmaf(hv.w, w3.x, acc[r][0]);
                acc[r][1] = fmaf(hv.w, w3.y, acc[r][1]);
                acc[r][2] = fmaf(hv.w, w3.z, acc[r][2]);
                acc[r][3] = fmaf(hv.w, w3.w, acc[r][3]);
            }
        }

#pragma unroll
        for (int r = 0; r < 2; r++) {
            const float c_new = creg[r] * sigm(acc[r][2] + 1.0f)
                              + sigm(acc[r][0]) * tanhf(acc[r][1]);
            const float h_new = tanhf(c_new) * sigm(acc[r][3]);
            creg[r] = c_new;
            const size_t off = ((size_t)t * BB + r0 + ty * 2 + r) * NHD + hu0 + tx;
            hs[off] = h_new;
            cs[off] = c_new;
            __nv_bfloat16 hb, lb;
            split2(h_new, hb, lb);
            g_hh[off] = hb;
            g_hl[off] = lb;
        }

        // cluster barrier: releases this block's h writes, acquires peers'
        CLUSTER_SYNC();
        hprev = hs + (size_t)t * BB * NHD;
    }
}

// ---------------------------------------------------------------------------
// Shared 128x128x128 HMMA chunk (split-2). 256 threads, 8 warps (32x64 tiles).
// A: pre-split bf16 hi/lo in global (row stride lda). B: fp32, split on stage.
// ---------------------------------------------------------------------------
#define SRA  136
#define A_HI 0u
#define A_LO 34816u
#define B_HI 69632u
#define B_LO 104448u
#define MM_SMEM 139264u

__device__ __forceinline__ void mma_chunk(
    const __nv_bfloat16* __restrict__ gAh, const __nv_bfloat16* __restrict__ gAl,
    int lda, const float* __restrict__ gB, int ldb,
    char* dsm, uint32_t base_u, float (&acc)[2][8][4])
{
    const int tid = threadIdx.x;
    const int wid = tid >> 5, lane = tid & 31;
    const int wm = wid & 3, wn = wid >> 2;
    const int lr = lane & 15, lc8 = (lane >> 4) << 3;

    __syncthreads();  // previous chunk's MMAs done
    for (int i = tid; i < 128 * 16; i += 256) {
        const int row = i >> 4, ch = i & 15;
        *(uint4*)(dsm + A_HI + 2 * (row * SRA + ch * 8)) =
            *(const uint4*)&gAh[(size_t)row * lda + ch * 8];
        *(uint4*)(dsm + A_LO + 2 * (row * SRA + ch * 8)) =
            *(const uint4*)&gAl[(size_t)row * lda + ch * 8];
    }
    for (int i = tid; i < 128 * 128; i += 256) {
        const int k = i >> 7, n = i & 127;
        __nv_bfloat16 hi, lo;
        split2(gB[(size_t)k * ldb + n], hi, lo);
        *(__nv_bfloat16*)(dsm + B_HI + 2 * (k * SRA + n)) = hi;
        *(__nv_bfloat16*)(dsm + B_LO + 2 * (k * SRA + n)) = lo;
    }
    __syncthreads();

#pragma unroll
    for (int kc = 0; kc < 8; kc++) {
        const int k = kc * 16;
        uint32_t ah[2][4], al[2][4];
#pragma unroll
        for (int mt = 0; mt < 2; mt++) {
            const uint32_t aoff = 2 * ((wm * 32 + mt * 16 + lr) * SRA + k + lc8);
            ldsm_x4(ah[mt][0], ah[mt][1], ah[mt][2], ah[mt][3], base_u + A_HI + aoff);
            ldsm_x4(al[mt][0], al[mt][1], al[mt][2], al[mt][3], base_u + A_LO + aoff);
        }
        uint32_t bh[8][2], bl[8][2];
#pragma unroll
        for (int p = 0; p < 4; p++) {
            const uint32_t boff = 2 * ((k + lr) * SRA + wn * 64 + p * 16 + lc8);
            ldsm_x4_t(bh[2*p][0], bh[2*p][1], bh[2*p+1][0], bh[2*p+1][1], base_u + B_HI + boff);
            ldsm_x4_t(bl[2*p][0], bl[2*p][1], bl[2*p+1][0], bl[2*p+1][1], base_u + B_LO + boff);
        }
#pragma unroll
        for (int mt = 0; mt < 2; mt++)
#pragma unroll
            for (int nt = 0; nt < 8; nt++) {
                mma16816(acc[mt][nt], ah[mt], bh[nt]);
                mma16816(acc[mt][nt], ah[mt], bl[nt]);
                mma16816(acc[mt][nt], al[mt], bh[nt]);
            }
    }
}

// bn = hs @ bneck_w ; writes fp32 bn_out + bf16 split g_bnh/g_bnl
__global__ void __launch_bounds__(256, 1)
bn_kernel(const float* __restrict__ bneck_w, float* __restrict__ bn_out)
{
    extern __shared__ __align__(16) char dsm[];
    const uint32_t base_u = smem_u32(dsm);
    const int tid = threadIdx.x;
    const int wid = tid >> 5, lane = tid & 31;
    const int wm = wid & 3, wn = wid >> 2;
    const int g = lane >> 2, tg2 = (lane & 3) * 2;
    const int m0 = blockIdx.x * 128, nh = blockIdx.y;

    float acc[2][8][4];
#pragma unroll
    for (int a = 0; a < 2; a++)
#pragma unroll
        for (int b = 0; b < 8; b++)
#pragma unroll
            for (int c = 0; c < 4; c++) acc[a][b][c] = 0.0f;

    mma_chunk(g_hh + (size_t)m0 * NHD, g_hl + (size_t)m0 * NHD, NHD,
              bneck_w + nh * 128, NBOT, dsm, base_u, acc);

#pragma unroll
    for (int mt = 0; mt < 2; mt++)
#pragma unroll
    for (int nt = 0; nt < 8; nt++) {
        const int row = m0 + wm * 32 + mt * 16 + g;
        const int col = nh * 128 + wn * 64 + nt * 8 + tg2;
        const float* a4 = acc[mt][nt];
        *(float2*)&bn_out[(size_t)row * 256 + col]       = make_float2(a4[0], a4[1]);
        *(float2*)&bn_out[(size_t)(row + 8) * 256 + col] = make_float2(a4[2], a4[3]);
        __nv_bfloat16 h0b, l0b, h1b, l1b;
        __nv_bfloat162 ph, pl;
        split2(a4[0], h0b, l0b); split2(a4[1], h1b, l1b);
        ph.x = h0b; ph.y = h1b; pl.x = l0b; pl.y = l1b;
        *(__nv_bfloat162*)&g_bnh[(size_t)row * 256 + col] = ph;
        *(__nv_bfloat162*)&g_bnl[(size_t)row * 256 + col] = pl;
        split2(a4[2], h0b, l0b); split2(a4[3], h1b, l1b);
        ph.x = h0b; ph.y = h1b; pl.x = l0b; pl.y = l1b;
        *(__nv_bfloat162*)&g_bnh[(size_t)(row + 8) * 256 + col] = ph;
        *(__nv_bfloat162*)&g_bnl[(size_t)(row + 8) * 256 + col] = pl;
    }
}

// pc = bn @ pc_w + pc_b   (K=256 in two chunks)
__global__ void __launch_bounds__(256, 1)
pc_kernel(const float* __restrict__ pc_w, const float* __restrict__ pc_b,
          float* __restrict__ pc_out)
{
    extern __shared__ __align__(16) char dsm[];
    const uint32_t base_u = smem_u32(dsm);
    const int tid = threadIdx.x;
    const int wid = tid >> 5, lane = tid & 31;
    const int wm = wid & 3, wn = wid >> 2;
    const int g = lane >> 2, tg2 = (lane & 3) * 2;
    const int m0 = blockIdx.x * 128, nh = blockIdx.y;

    float acc[2][8][4];
#pragma unroll
    for (int a = 0; a < 2; a++)
#pragma unroll
        for (int b = 0; b < 8; b++)
#pragma unroll
            for (int c = 0; c < 4; c++) acc[a][b][c] = 0.0f;

#pragma unroll 1
    for (int kc = 0; kc < 2; kc++)
        mma_chunk(g_bnh + (size_t)m0 * NBOT + kc * 128,
                  g_bnl + (size_t)m0 * NBOT + kc * 128, NBOT,
                  pc_w + (size_t)kc * 128 * NPC + nh * 128, NPC, dsm, base_u, acc);

#pragma unroll
    for (int mt = 0; mt < 2; mt++)
#pragma unroll
    for (int nt = 0; nt < 8; nt++) {
        const int row = m0 + wm * 32 + mt * 16 + g;
        const int col = nh * 128 + wn * 64 + nt * 8 + tg2;
        const float b0 = __ldg(&pc_b[col]), b1 = __ldg(&pc_b[col + 1]);
        const float* a4 = acc[mt][nt];
        *(float2*)&pc_out[(size_t)row * 256 + col] = make_float2(a4[0] + b0, a4[1] + b1);
        *(float2*)&pc_out[(size_t)(row + 8) * 256 + col] = make_float2(a4[2] + b0, a4[3] + b1);
    }
}

// hd = bn @ hd_w + hd_b  (fp32, exact; 32 rows per block)
__global__ void __launch_bounds__(256, 1)
hd_kernel(const float* __restrict__ bn, const float* __restrict__ hd_w,
          const float* __restrict__ hd_b, float* __restrict__ hd_out)
{
    __shared__ float bn_s[32 * 257];
    __shared__ float w_s[256 * 12];
    const int tid = threadIdx.x;
    const int m0 = blockIdx.x * 32;

    for (int i = tid; i < 32 * 256; i += 256) {
        const int row = i >> 8, k = i & 255;
        bn_s[row * 257 + k] = bn[(size_t)(m0 + row) * 256 + k];
    }
    for (int i = tid; i < 256 * 12; i += 256) w_s[i] = hd_w[i];
    __syncthreads();

#pragma unroll
    for (int p = 0; p < 2; p++) {
        const int o = tid + p * 256;
        if (o < 384) {
            const int row = o / 12, n = o % 12;
            float s = hd_b[n];
            const float* br = &bn_s[row * 257];
#pragma unroll 8
            for (int k = 0; k < 256; k++) s = fmaf(br[k], w_s[k * 12 + n], s);
            hd_out[(size_t)(m0 + row) * 12 + n] = s;
        }
    }
}

// ---------------------------------------------------------------------------
extern "C" void kernel_launch(void* const* d_in, const int* in_sizes, int n_in,
                              void* d_out, int out_size)
{
    const float* x       = (const float*)d_in[0];
    const float* init    = (const float*)d_in[1];
    const float* rnn_w   = (const float*)d_in[2];
    const float* rnn_b   = (const float*)d_in[3];
    const float* state_w = (const float*)d_in[4];
    const float* state_b = (const float*)d_in[5];
    const float* cell_w  = (const float*)d_in[6];
    const float* cell_b  = (const float*)d_in[7];
    const float* bneck_w = (const float*)d_in[8];
    const float* pc_w    = (const float*)d_in[9];
    const float* pc_b    = (const float*)d_in[10];
    const float* hd_w    = (const float*)d_in[11];
    const float* hd_b    = (const float*)d_in[12];

    float* out = (float*)d_out;
    float* hd_out = out;
    float* pc_out = hd_out + (size_t)TB * NHDC;
    float* bn_out = pc_out + (size_t)TB * NPC;
    float* hs_out = bn_out + (size_t)TB * NBOT;
    float* cs_out = hs_out + (size_t)TB * NHD;

    float *h0p = nullptr, *c0p = nullptr;
    cudaGetSymbolAddress((void**)&h0p, g_h0);
    cudaGetSymbolAddress((void**)&c0p, g_c0);

    cudaFuncSetAttribute(lstm_kernel, cudaFuncAttributeMaxDynamicSharedMemorySize, LSTM_SMEM);
    cudaFuncSetAttribute(bn_kernel, cudaFuncAttributeMaxDynamicSharedMemorySize, MM_SMEM);
    cudaFuncSetAttribute(pc_kernel, cudaFuncAttributeMaxDynamicSharedMemorySize, MM_SMEM);

    gemm_kernel<<<dim3(2, 16), 256>>>(init, state_w, state_b, h0p, BB, NHD, NIC);
    gemm_kernel<<<dim3(2, 16), 256>>>(init, cell_w,  cell_b,  c0p, BB, NHD, NIC);

    lstm_kernel<<<128, 512, LSTM_SMEM>>>(x, rnn_w, rnn_b, hs_out, cs_out);

    bn_kernel<<<dim3(TB / 128, 2), 256, MM_SMEM>>>(bneck_w, bn_out);
    pc_kernel<<<dim3(TB / 128, 2), 256, MM_SMEM>>>(pc_w, pc_b, pc_out);
    hd_kernel<<<TB / 32, 256>>>(bn_out, hd_w, hd_b, hd_out);
}

// round 6
// speedup vs baseline: 1.6024x; 1.6024x over previous
#include <cuda_runtime.h>
#include <cuda_bf16.h>
#include <cstdint>
#include <cstddef>

#define TT   100
#define BB   1024
#define NHD  128
#define NGATE 512
#define NIC  268
#define NBOT 256
#define NPC  256
#define NHDC 12
#define TB   (TT * BB)

// ---------------------------------------------------------------------------
// device scratch
// ---------------------------------------------------------------------------
__device__ float g_h0[BB * NHD];
__device__ float g_c0[BB * NHD];
__device__ __nv_bfloat16 g_hh[(size_t)TB * NHD];
__device__ __nv_bfloat16 g_hl[(size_t)TB * NHD];
__device__ __nv_bfloat16 g_bnh[(size_t)TB * NBOT];
__device__ __nv_bfloat16 g_bnl[(size_t)TB * NBOT];
__device__ __nv_bfloat16 g_bwh[NHD * NBOT], g_bwl[NHD * NBOT];
__device__ __nv_bfloat16 g_pwh[NBOT * NPC], g_pwl[NBOT * NPC];
// per-row-tile group barriers (16 groups of 8 blocks)
__device__ unsigned g_cnt16[16];
__device__ volatile unsigned g_gen16[16];

__device__ __forceinline__ float sigm(float v) { return 1.0f / (1.0f + __expf(-v)); }
__device__ __forceinline__ void split2(float v, __nv_bfloat16& hi, __nv_bfloat16& lo) {
    hi = __float2bfloat16(v);
    lo = __float2bfloat16(v - __bfloat162float(hi));
}
__device__ __forceinline__ uint32_t smem_u32(const void* p) {
    uint32_t a;
    asm("{ .reg .u64 t; cvta.to.shared.u64 t, %1; cvt.u32.u64 %0, t; }" : "=r"(a) : "l"(p));
    return a;
}
__device__ __forceinline__ void ldsm_x4(uint32_t& r0, uint32_t& r1, uint32_t& r2,
                                        uint32_t& r3, uint32_t addr) {
    asm volatile("ldmatrix.sync.aligned.m8n8.x4.shared.b16 {%0,%1,%2,%3}, [%4];"
                 : "=r"(r0), "=r"(r1), "=r"(r2), "=r"(r3) : "r"(addr));
}
__device__ __forceinline__ void ldsm_x4_t(uint32_t& r0, uint32_t& r1, uint32_t& r2,
                                          uint32_t& r3, uint32_t addr) {
    asm volatile("ldmatrix.sync.aligned.m8n8.x4.trans.shared.b16 {%0,%1,%2,%3}, [%4];"
                 : "=r"(r0), "=r"(r1), "=r"(r2), "=r"(r3) : "r"(addr));
}
__device__ __forceinline__ void mma16816(float* d, const uint32_t* a, const uint32_t* b) {
    asm volatile(
        "mma.sync.aligned.m16n8k16.row.col.f32.bf16.bf16.f32 "
        "{%0,%1,%2,%3}, {%4,%5,%6,%7}, {%8,%9}, {%0,%1,%2,%3};"
        : "+f"(d[0]), "+f"(d[1]), "+f"(d[2]), "+f"(d[3])
        : "r"(a[0]), "r"(a[1]), "r"(a[2]), "r"(a[3]), "r"(b[0]), "r"(b[1]));
}

// ---------------------------------------------------------------------------
// weight pre-split (bneck_w, pc_w) -> bf16 hi/lo
// ---------------------------------------------------------------------------
__global__ void split_w_kernel(const float* __restrict__ bw, const float* __restrict__ pw)
{
    const int i = blockIdx.x * 256 + threadIdx.x;
    if (i < NHD * NBOT) {
        __nv_bfloat16 hi, lo;
        split2(bw[i], hi, lo);
        g_bwh[i] = hi; g_bwl[i] = lo;
    } else if (i < NHD * NBOT + NBOT * NPC) {
        const int j = i - NHD * NBOT;
        __nv_bfloat16 hi, lo;
        split2(pw[j], hi, lo);
        g_pwh[j] = hi; g_pwl[j] = lo;
    }
}

// ---------------------------------------------------------------------------
// fp32 GEMM for h0/c0 init
// ---------------------------------------------------------------------------
__global__ void gemm_kernel(const float* __restrict__ A, const float* __restrict__ W,
                            const float* __restrict__ bias, float* __restrict__ C,
                            int M, int N, int K)
{
    __shared__ float As[16][68];
    __shared__ float Ws[16][68];
    const int tid = threadIdx.x;
    const int tx = tid & 15, ty = tid >> 4;
    const int n0 = blockIdx.x * 64, m0 = blockIdx.y * 64;

    float acc[4][4];
#pragma unroll
    for (int r = 0; r < 4; r++)
#pragma unroll
        for (int q = 0; q < 4; q++) acc[r][q] = 0.0f;

    for (int k0 = 0; k0 < K; k0 += 16) {
        {
            const int k = tid & 15, m = tid >> 4;
#pragma unroll
            for (int p = 0; p < 4; p++) {
                const int mm = m + p * 16;
                float v = 0.0f;
                if (k0 + k < K) v = A[(size_t)(m0 + mm) * K + (k0 + k)];
                As[k][mm] = v;
            }
        }
        {
            const int n = tid & 63, kb = tid >> 6;
#pragma unroll
            for (int p = 0; p < 4; p++) {
                const int kk = kb + p * 4;
                float v = 0.0f;
                if ((k0 + kk < K) && (n0 + n < N)) v = W[(size_t)(k0 + kk) * N + (n0 + n)];
                Ws[kk][n] = v;
            }
        }
        __syncthreads();
#pragma unroll
        for (int kk = 0; kk < 16; kk++) {
            const float4 a4 = *(const float4*)&As[kk][ty * 4];
            const float4 b4 = *(const float4*)&Ws[kk][tx * 4];
            const float av[4] = {a4.x, a4.y, a4.z, a4.w};
            const float bv[4] = {b4.x, b4.y, b4.z, b4.w};
#pragma unroll
            for (int r = 0; r < 4; r++)
#pragma unroll
                for (int q = 0; q < 4; q++)
                    acc[r][q] = fmaf(av[r], bv[q], acc[r][q]);
        }
        __syncthreads();
    }
#pragma unroll
    for (int r = 0; r < 4; r++) {
        const int m = m0 + ty * 4 + r;
#pragma unroll
        for (int q = 0; q < 4; q++) {
            const int n = n0 + tx * 4 + q;
            if (n < N) C[(size_t)m * N + n] = acc[r][q] + (bias ? bias[n] : 0.0f);
        }
    }
}

// ---------------------------------------------------------------------------
// LSTM recurrence: 128 persistent blocks, 512 threads.
// Block (rt, cg): rows [rt*64, rt*64+64), units [cg*16, cg*16+16).
// Per-step sync: per-group (rt) 8-block atomic barrier — blocks only wait on
// the 7 peers producing the h values they actually read.
// ---------------------------------------------------------------------------
#define LSTM_SMEM ((128 * 64 + 64 * 128 + 3 * 64 + 64 + 64 * 4) * 4)

__global__ void __launch_bounds__(512, 1)
lstm_kernel(const float* __restrict__ x, const float* __restrict__ rnn_w,
            const float* __restrict__ rnn_b,
            float* __restrict__ hs, float* __restrict__ cs)
{
    extern __shared__ float sm[];
    float* wh_s = sm;              // [128][64]
    float* h_s  = sm + 8192;       // [64][128]
    float* wx_s = h_s + 8192;      // [3][64]
    float* b_s  = wx_s + 192;      // [64]
    float* x_s  = b_s + 64;        // [64][4]

    const int tid = threadIdx.x;
    const int tx = tid & 15, ty = tid >> 4;
    const int cg = blockIdx.x & 7;
    const int rt = blockIdx.x >> 3;
    const int r0 = rt * 64;
    const int hu0 = cg * 16;

    for (int idx = tid; idx < 128 * 64; idx += 512) {
        const int k = idx >> 6, c = idx & 63;
        const int u = c >> 2, q = c & 3;
        wh_s[idx] = rnn_w[(size_t)(3 + k) * NGATE + q * NHD + hu0 + u];
    }
    if (tid < 192) {
        const int m = tid >> 6, c = tid & 63;
        const int u = c >> 2, q = c & 3;
        wx_s[m * 64 + c] = rnn_w[(size_t)m * NGATE + q * NHD + hu0 + u];
    }
    if (tid < 64) {
        const int u = tid >> 2, q = tid & 3;
        b_s[tid] = rnn_b[q * NHD + hu0 + u];
    }

    float creg[2];
#pragma unroll
    for (int r = 0; r < 2; r++)
        creg[r] = g_c0[(size_t)(r0 + ty * 2 + r) * NHD + hu0 + tx];

    const float* hprev = g_h0;

    for (int t = 0; t < TT; t++) {
        for (int i = tid; i < 64 * 32; i += 512) {
            const int row = i >> 5, c4 = i & 31;
            *(float4*)&h_s[row * 128 + c4 * 4] =
                *(const float4*)&hprev[(size_t)(r0 + row) * NHD + c4 * 4];
        }
        if (tid < 64) {
            const float* xp = x + ((size_t)t * BB + r0 + tid) * 3;
            x_s[tid * 4 + 0] = xp[0];
            x_s[tid * 4 + 1] = xp[1];
            x_s[tid * 4 + 2] = xp[2];
        }
        __syncthreads();

        float acc[2][4];
#pragma unroll
        for (int r = 0; r < 2; r++) {
            const float x0 = x_s[(ty * 2 + r) * 4 + 0];
            const float x1 = x_s[(ty * 2 + r) * 4 + 1];
            const float x2 = x_s[(ty * 2 + r) * 4 + 2];
#pragma unroll
            for (int q = 0; q < 4; q++) {
                const int c = tx * 4 + q;
                float v = b_s[c];
                v = fmaf(x0, wx_s[c], v);
                v = fmaf(x1, wx_s[64 + c], v);
                v = fmaf(x2, wx_s[128 + c], v);
                acc[r][q] = v;
            }
        }

#pragma unroll 4
        for (int k = 0; k < 128; k += 4) {
            const float4 w0 = *(const float4*)&wh_s[(k + 0) * 64 + tx * 4];
            const float4 w1 = *(const float4*)&wh_s[(k + 1) * 64 + tx * 4];
            const float4 w2 = *(const float4*)&wh_s[(k + 2) * 64 + tx * 4];
            const float4 w3 = *(const float4*)&wh_s[(k + 3) * 64 + tx * 4];
#pragma unroll
            for (int r = 0; r < 2; r++) {
                const float4 hv = *(const float4*)&h_s[(ty * 2 + r) * 128 + k];
                acc[r][0] = fmaf(hv.x, w0.x, acc[r][0]);
                acc[r][1] = fmaf(hv.x, w0.y, acc[r][1]);
                acc[r][2] = fmaf(hv.x, w0.z, acc[r][2]);
                acc[r][3] = fmaf(hv.x, w0.w, acc[r][3]);
                acc[r][0] = fmaf(hv.y, w1.x, acc[r][0]);
                acc[r][1] = fmaf(hv.y, w1.y, acc[r][1]);
                acc[r][2] = fmaf(hv.y, w1.z, acc[r][2]);
                acc[r][3] = fmaf(hv.y, w1.w, acc[r][3]);
                acc[r][0] = fmaf(hv.z, w2.x, acc[r][0]);
                acc[r][1] = fmaf(hv.z, w2.y, acc[r][1]);
                acc[r][2] = fmaf(hv.z, w2.z, acc[r][2]);
                acc[r][3] = fmaf(hv.z, w2.w, acc[r][3]);
                acc[r][0] = fmaf(hv.w, w3.x, acc[r][0]);
                acc[r][1] = fmaf(hv.w, w3.y, acc[r][1]);
                acc[r][2] = fmaf(hv.w, w3.z, acc[r][2]);
                acc[r][3] = fmaf(hv.w, w3.w, acc[r][3]);
            }
        }

#pragma unroll
        for (int r = 0; r < 2; r++) {
            const float c_new = creg[r] * sigm(acc[r][2] + 1.0f)
                              + sigm(acc[r][0]) * tanhf(acc[r][1]);
            const float h_new = tanhf(c_new) * sigm(acc[r][3]);
            creg[r] = c_new;
            const size_t off = ((size_t)t * BB + r0 + ty * 2 + r) * NHD + hu0 + tx;
            hs[off] = h_new;
            cs[off] = c_new;
            __nv_bfloat16 hb, lb;
            split2(h_new, hb, lb);
            g_hh[off] = hb;
            g_hl[off] = lb;
        }

        // per-group barrier (8 blocks of row-tile rt)
        __threadfence();
        __syncthreads();
        if (tid == 0) {
            const unsigned gen = g_gen16[rt];
            if (atomicAdd(&g_cnt16[rt], 1u) == 7u) {
                g_cnt16[rt] = 0u;
                __threadfence();
                g_gen16[rt] = gen + 1u;
            } else {
                while (g_gen16[rt] == gen) { }
            }
        }
        __syncthreads();

        hprev = hs + (size_t)t * BB * NHD;
    }
}

// ---------------------------------------------------------------------------
// HMMA GEMM chunk: block tile M128 x N128, K=128, 512 threads (16 warps, 4x4).
// All operands pre-split bf16 hi/lo in global — staging is pure uint4 copies.
// ---------------------------------------------------------------------------
#define SRA  136
#define A_HI 0u
#define A_LO 34816u
#define B_HI 69632u
#define B_LO 104448u
#define MM_SMEM 139264u

__device__ __forceinline__ void mma_chunk_bf16(
    const __nv_bfloat16* __restrict__ gAh, const __nv_bfloat16* __restrict__ gAl, int lda,
    const __nv_bfloat16* __restrict__ gBh, const __nv_bfloat16* __restrict__ gBl, int ldb,
    char* dsm, uint32_t base_u, float (&acc)[2][4][4])
{
    const int tid = threadIdx.x;
    const int wid = tid >> 5, lane = tid & 31;
    const int wm = wid & 3, wn = wid >> 2;
    const int lr = lane & 15, lc8 = (lane >> 4) << 3;

    __syncthreads();
    for (int i = tid; i < 128 * 16; i += 512) {
        const int row = i >> 4, ch = i & 15;
        *(uint4*)(dsm + A_HI + 2 * (row * SRA + ch * 8)) =
            *(const uint4*)&gAh[(size_t)row * lda + ch * 8];
        *(uint4*)(dsm + A_LO + 2 * (row * SRA + ch * 8)) =
            *(const uint4*)&gAl[(size_t)row * lda + ch * 8];
        *(uint4*)(dsm + B_HI + 2 * (row * SRA + ch * 8)) =
            *(const uint4*)&gBh[(size_t)row * ldb + ch * 8];
        *(uint4*)(dsm + B_LO + 2 * (row * SRA + ch * 8)) =
            *(const uint4*)&gBl[(size_t)row * ldb + ch * 8];
    }
    __syncthreads();

#pragma unroll
    for (int kc = 0; kc < 8; kc++) {
        const int k = kc * 16;
        uint32_t ah[2][4], al[2][4];
#pragma unroll
        for (int mt = 0; mt < 2; mt++) {
            const uint32_t aoff = 2 * ((wm * 32 + mt * 16 + lr) * SRA + k + lc8);
            ldsm_x4(ah[mt][0], ah[mt][1], ah[mt][2], ah[mt][3], base_u + A_HI + aoff);
            ldsm_x4(al[mt][0], al[mt][1], al[mt][2], al[mt][3], base_u + A_LO + aoff);
        }
        uint32_t bh[4][2], bl[4][2];
#pragma unroll
        for (int p = 0; p < 2; p++) {
            const uint32_t boff = 2 * ((k + lr) * SRA + wn * 32 + p * 16 + lc8);
            ldsm_x4_t(bh[2*p][0], bh[2*p][1], bh[2*p+1][0], bh[2*p+1][1], base_u + B_HI + boff);
            ldsm_x4_t(bl[2*p][0], bl[2*p][1], bl[2*p+1][0], bl[2*p+1][1], base_u + B_LO + boff);
        }
#pragma unroll
        for (int mt = 0; mt < 2; mt++)
#pragma unroll
            for (int nt = 0; nt < 4; nt++) {
                mma16816(acc[mt][nt], ah[mt], bh[nt]);
                mma16816(acc[mt][nt], ah[mt], bl[nt]);
                mma16816(acc[mt][nt], al[mt], bh[nt]);
            }
    }
}

// bn = hs @ bneck_w  -> fp32 bn_out + bf16 split g_bnh/g_bnl
__global__ void __launch_bounds__(512, 1)
bn_kernel(float* __restrict__ bn_out)
{
    extern __shared__ __align__(16) char dsm[];
    const uint32_t base_u = smem_u32(dsm);
    const int tid = threadIdx.x;
    const int wid = tid >> 5, lane = tid & 31;
    const int wm = wid & 3, wn = wid >> 2;
    const int g = lane >> 2, tg2 = (lane & 3) * 2;
    const int m0 = blockIdx.x * 128, nh = blockIdx.y;

    float acc[2][4][4];
#pragma unroll
    for (int a = 0; a < 2; a++)
#pragma unroll
        for (int b = 0; b < 4; b++)
#pragma unroll
            for (int c = 0; c < 4; c++) acc[a][b][c] = 0.0f;

    mma_chunk_bf16(g_hh + (size_t)m0 * NHD, g_hl + (size_t)m0 * NHD, NHD,
                   g_bwh + nh * 128, g_bwl + nh * 128, NBOT, dsm, base_u, acc);

#pragma unroll
    for (int mt = 0; mt < 2; mt++)
#pragma unroll
    for (int nt = 0; nt < 4; nt++) {
        const int row = m0 + wm * 32 + mt * 16 + g;
        const int col = nh * 128 + wn * 32 + nt * 8 + tg2;
        const float* a4 = acc[mt][nt];
        *(float2*)&bn_out[(size_t)row * 256 + col]       = make_float2(a4[0], a4[1]);
        *(float2*)&bn_out[(size_t)(row + 8) * 256 + col] = make_float2(a4[2], a4[3]);
        __nv_bfloat16 h0b, l0b, h1b, l1b;
        __nv_bfloat162 ph, pl;
        split2(a4[0], h0b, l0b); split2(a4[1], h1b, l1b);
        ph.x = h0b; ph.y = h1b; pl.x = l0b; pl.y = l1b;
        *(__nv_bfloat162*)&g_bnh[(size_t)row * 256 + col] = ph;
        *(__nv_bfloat162*)&g_bnl[(size_t)row * 256 + col] = pl;
        split2(a4[2], h0b, l0b); split2(a4[3], h1b, l1b);
        ph.x = h0b; ph.y = h1b; pl.x = l0b; pl.y = l1b;
        *(__nv_bfloat162*)&g_bnh[(size_t)(row + 8) * 256 + col] = ph;
        *(__nv_bfloat162*)&g_bnl[(size_t)(row + 8) * 256 + col] = pl;
    }
}

// pc = bn @ pc_w + pc_b   (K=256: two chunks)
__global__ void __launch_bounds__(512, 1)
pc_kernel(const float* __restrict__ pc_b, float* __restrict__ pc_out)
{
    extern __shared__ __align__(16) char dsm[];
    const uint32_t base_u = smem_u32(dsm);
    const int tid = threadIdx.x;
    const int wid = tid >> 5, lane = tid & 31;
    const int wm = wid & 3, wn = wid >> 2;
    const int g = lane >> 2, tg2 = (lane & 3) * 2;
    const int m0 = blockIdx.x * 128, nh = blockIdx.y;

    float acc[2][4][4];
#pragma unroll
    for (int a = 0; a < 2; a++)
#pragma unroll
        for (int b = 0; b < 4; b++)
#pragma unroll
            for (int c = 0; c < 4; c++) acc[a][b][c] = 0.0f;

#pragma unroll 1
    for (int kc = 0; kc < 2; kc++)
        mma_chunk_bf16(g_bnh + (size_t)m0 * NBOT + kc * 128,
                       g_bnl + (size_t)m0 * NBOT + kc * 128, NBOT,
                       g_pwh + (size_t)kc * 128 * NPC + nh * 128,
                       g_pwl + (size_t)kc * 128 * NPC + nh * 128, NPC,
                       dsm, base_u, acc);

#pragma unroll
    for (int mt = 0; mt < 2; mt++)
#pragma unroll
    for (int nt = 0; nt < 4; nt++) {
        const int row = m0 + wm * 32 + mt * 16 + g;
        const int col = nh * 128 + wn * 32 + nt * 8 + tg2;
        const float b0 = __ldg(&pc_b[col]), b1 = __ldg(&pc_b[col + 1]);
        const float* a4 = acc[mt][nt];
        *(float2*)&pc_out[(size_t)row * 256 + col] = make_float2(a4[0] + b0, a4[1] + b1);
        *(float2*)&pc_out[(size_t)(row + 8) * 256 + col] = make_float2(a4[2] + b0, a4[3] + b1);
    }
}

// hd = bn @ hd_w + hd_b  (fp32)
__global__ void __launch_bounds__(256, 1)
hd_kernel(const float* __restrict__ bn, const float* __restrict__ hd_w,
          const float* __restrict__ hd_b, float* __restrict__ hd_out)
{
    __shared__ float bn_s[32 * 257];
    __shared__ float w_s[256 * 12];
    const int tid = threadIdx.x;
    const int m0 = blockIdx.x * 32;

    for (int i = tid; i < 32 * 256; i += 256) {
        const int row = i >> 8, k = i & 255;
        bn_s[row * 257 + k] = bn[(size_t)(m0 + row) * 256 + k];
    }
    for (int i = tid; i < 256 * 12; i += 256) w_s[i] = hd_w[i];
    __syncthreads();

#pragma unroll
    for (int p = 0; p < 2; p++) {
        const int o = tid + p * 256;
        if (o < 384) {
            const int row = o / 12, n = o % 12;
            float s = hd_b[n];
            const float* br = &bn_s[row * 257];
#pragma unroll 8
            for (int k = 0; k < 256; k++) s = fmaf(br[k], w_s[k * 12 + n], s);
            hd_out[(size_t)(m0 + row) * 12 + n] = s;
        }
    }
}

// ---------------------------------------------------------------------------
extern "C" void kernel_launch(void* const* d_in, const int* in_sizes, int n_in,
                              void* d_out, int out_size)
{
    const float* x       = (const float*)d_in[0];
    const float* init    = (const float*)d_in[1];
    const float* rnn_w   = (const float*)d_in[2];
    const float* rnn_b   = (const float*)d_in[3];
    const float* state_w = (const float*)d_in[4];
    const float* state_b = (const float*)d_in[5];
    const float* cell_w  = (const float*)d_in[6];
    const float* cell_b  = (const float*)d_in[7];
    const float* bneck_w = (const float*)d_in[8];
    const float* pc_w    = (const float*)d_in[9];
    const float* pc_b    = (const float*)d_in[10];
    const float* hd_w    = (const float*)d_in[11];
    const float* hd_b    = (const float*)d_in[12];

    float* out = (float*)d_out;
    float* hd_out = out;
    float* pc_out = hd_out + (size_t)TB * NHDC;
    float* bn_out = pc_out + (size_t)TB * NPC;
    float* hs_out = bn_out + (size_t)TB * NBOT;
    float* cs_out = hs_out + (size_t)TB * NHD;

    float *h0p = nullptr, *c0p = nullptr;
    cudaGetSymbolAddress((void**)&h0p, g_h0);
    cudaGetSymbolAddress((void**)&c0p, g_c0);

    cudaFuncSetAttribute(lstm_kernel, cudaFuncAttributeMaxDynamicSharedMemorySize, LSTM_SMEM);
    cudaFuncSetAttribute(bn_kernel, cudaFuncAttributeMaxDynamicSharedMemorySize, MM_SMEM);
    cudaFuncSetAttribute(pc_kernel, cudaFuncAttributeMaxDynamicSharedMemorySize, MM_SMEM);

    gemm_kernel<<<dim3(2, 16), 256>>>(init, state_w, state_b, h0p, BB, NHD, NIC);
    gemm_kernel<<<dim3(2, 16), 256>>>(init, cell_w,  cell_b,  c0p, BB, NHD, NIC);
    split_w_kernel<<<(NHD * NBOT + NBOT * NPC + 255) / 256, 256>>>(bneck_w, pc_w);

    lstm_kernel<<<128, 512, LSTM_SMEM>>>(x, rnn_w, rnn_b, hs_out, cs_out);

    bn_kernel<<<dim3(TB / 128, 2), 512, MM_SMEM>>>(bn_out);
    pc_kernel<<<dim3(TB / 128, 2), 512, MM_SMEM>>>(pc_b, pc_out);
    hd_kernel<<<TB / 32, 256>>>(bn_out, hd_w, hd_b, hd_out);
}

// round 7
// speedup vs baseline: 2.0999x; 1.3105x over previous
#include <cuda_runtime.h>
#include <cuda_bf16.h>
#include <cstdint>
#include <cstddef>

#define TT   100
#define BB   1024
#define NHD  128
#define NGATE 512
#define NIC  268
#define NBOT 256
#define NPC  256
#define NHDC 12
#define TB   (TT * BB)

// ---------------------------------------------------------------------------
// device scratch
// ---------------------------------------------------------------------------
__device__ float g_c0[BB * NHD];
// h history pre-split bf16: slot 0 = h0, slot t+1 = h_t   [(TT+1), BB, NHD]
__device__ __nv_bfloat16 g_hh[(size_t)(TT + 1) * BB * NHD];
__device__ __nv_bfloat16 g_hl[(size_t)(TT + 1) * BB * NHD];
__device__ __nv_bfloat16 g_bnh[(size_t)TB * NBOT];
__device__ __nv_bfloat16 g_bnl[(size_t)TB * NBOT];
__device__ __nv_bfloat16 g_bwh[NHD * NBOT], g_bwl[NHD * NBOT];
__device__ __nv_bfloat16 g_pwh[NBOT * NPC], g_pwl[NBOT * NPC];
// per-row-tile group barriers (16 groups of 8 blocks)
__device__ unsigned g_cnt16[16];
__device__ volatile unsigned g_gen16[16];

__device__ __forceinline__ float sigm(float v) { return 1.0f / (1.0f + __expf(-v)); }
__device__ __forceinline__ void split2(float v, __nv_bfloat16& hi, __nv_bfloat16& lo) {
    hi = __float2bfloat16(v);
    lo = __float2bfloat16(v - __bfloat162float(hi));
}
__device__ __forceinline__ uint32_t smem_u32(const void* p) {
    uint32_t a;
    asm("{ .reg .u64 t; cvta.to.shared.u64 t, %1; cvt.u32.u64 %0, t; }" : "=r"(a) : "l"(p));
    return a;
}
__device__ __forceinline__ void ldsm_x4(uint32_t& r0, uint32_t& r1, uint32_t& r2,
                                        uint32_t& r3, uint32_t addr) {
    asm volatile("ldmatrix.sync.aligned.m8n8.x4.shared.b16 {%0,%1,%2,%3}, [%4];"
                 : "=r"(r0), "=r"(r1), "=r"(r2), "=r"(r3) : "r"(addr));
}
__device__ __forceinline__ void ldsm_x4_t(uint32_t& r0, uint32_t& r1, uint32_t& r2,
                                          uint32_t& r3, uint32_t addr) {
    asm volatile("ldmatrix.sync.aligned.m8n8.x4.trans.shared.b16 {%0,%1,%2,%3}, [%4];"
                 : "=r"(r0), "=r"(r1), "=r"(r2), "=r"(r3) : "r"(addr));
}
__device__ __forceinline__ void mma16816(float* d, const uint32_t* a, const uint32_t* b) {
    asm volatile(
        "mma.sync.aligned.m16n8k16.row.col.f32.bf16.bf16.f32 "
        "{%0,%1,%2,%3}, {%4,%5,%6,%7}, {%8,%9}, {%0,%1,%2,%3};"
        : "+f"(d[0]), "+f"(d[1]), "+f"(d[2]), "+f"(d[3])
        : "r"(a[0]), "r"(a[1]), "r"(a[2]), "r"(a[3]), "r"(b[0]), "r"(b[1]));
}

// ---------------------------------------------------------------------------
// weight pre-split (bneck_w, pc_w)
// ---------------------------------------------------------------------------
__global__ void split_w_kernel(const float* __restrict__ bw, const float* __restrict__ pw)
{
    const int i = blockIdx.x * 256 + threadIdx.x;
    if (i < NHD * NBOT) {
        __nv_bfloat16 hi, lo;
        split2(bw[i], hi, lo);
        g_bwh[i] = hi; g_bwl[i] = lo;
    } else if (i < NHD * NBOT + NBOT * NPC) {
        const int j = i - NHD * NBOT;
        __nv_bfloat16 hi, lo;
        split2(pw[j], hi, lo);
        g_pwh[j] = hi; g_pwl[j] = lo;
    }
}

// ---------------------------------------------------------------------------
// fp32 GEMM for h0/c0 init; optional bf16 hi/lo emission (for h0 -> slot 0)
// ---------------------------------------------------------------------------
__global__ void gemm_kernel(const float* __restrict__ A, const float* __restrict__ W,
                            const float* __restrict__ bias, float* __restrict__ C,
                            __nv_bfloat16* __restrict__ oh, __nv_bfloat16* __restrict__ ol,
                            int M, int N, int K)
{
    __shared__ float As[16][68];
    __shared__ float Ws[16][68];
    const int tid = threadIdx.x;
    const int tx = tid & 15, ty = tid >> 4;
    const int n0 = blockIdx.x * 64, m0 = blockIdx.y * 64;

    float acc[4][4];
#pragma unroll
    for (int r = 0; r < 4; r++)
#pragma unroll
        for (int q = 0; q < 4; q++) acc[r][q] = 0.0f;

    for (int k0 = 0; k0 < K; k0 += 16) {
        {
            const int k = tid & 15, m = tid >> 4;
#pragma unroll
            for (int p = 0; p < 4; p++) {
                const int mm = m + p * 16;
                float v = 0.0f;
                if (k0 + k < K) v = A[(size_t)(m0 + mm) * K + (k0 + k)];
                As[k][mm] = v;
            }
        }
        {
            const int n = tid & 63, kb = tid >> 6;
#pragma unroll
            for (int p = 0; p < 4; p++) {
                const int kk = kb + p * 4;
                float v = 0.0f;
                if ((k0 + kk < K) && (n0 + n < N)) v = W[(size_t)(k0 + kk) * N + (n0 + n)];
                Ws[kk][n] = v;
            }
        }
        __syncthreads();
#pragma unroll
        for (int kk = 0; kk < 16; kk++) {
            const float4 a4 = *(const float4*)&As[kk][ty * 4];
            const float4 b4 = *(const float4*)&Ws[kk][tx * 4];
            const float av[4] = {a4.x, a4.y, a4.z, a4.w};
            const float bv[4] = {b4.x, b4.y, b4.z, b4.w};
#pragma unroll
            for (int r = 0; r < 4; r++)
#pragma unroll
                for (int q = 0; q < 4; q++)
                    acc[r][q] = fmaf(av[r], bv[q], acc[r][q]);
        }
        __syncthreads();
    }
#pragma unroll
    for (int r = 0; r < 4; r++) {
        const int m = m0 + ty * 4 + r;
#pragma unroll
        for (int q = 0; q < 4; q++) {
            const int n = n0 + tx * 4 + q;
            if (n < N) {
                const float v = acc[r][q] + (bias ? bias[n] : 0.0f);
                C[(size_t)m * N + n] = v;
                if (oh) {
                    __nv_bfloat16 hi, lo;
                    split2(v, hi, lo);
                    oh[(size_t)m * N + n] = hi;
                    ol[(size_t)m * N + n] = lo;
                }
            }
        }
    }
}

// ---------------------------------------------------------------------------
// LSTM recurrence on HMMA (4-term bf16 split = fp32-exact gate products).
// 128 persistent blocks (16 row-tiles x 8 unit-groups), 512 threads (16 warps).
// Block: rows [rt*64,+64), units [cg*16,+16) -> 64 gate cols (c = u*4+q).
// Warp (wm=wid&3, wn=wid>>2): 16 rows x 16 gate-cols.
// Per-step sync: per-row-tile 8-block atomic barrier.
// ---------------------------------------------------------------------------
#define L_WHH 0u          // [128][72] bf16
#define L_WHL 18432u
#define L_AHI 36864u      // [64][136] bf16
#define L_ALO 54272u
#define L_XS  71680u      // [64][4] f32
#define L_WX  72704u      // [3][64] f32
#define L_BS  73472u      // [64] f32
#define L_HST 73728u      // [64][20] f32
#define L_CST 78848u
#define LSTM_SMEM 83968u
#define SWH 72
#define SAH 136
#define SHT 20

__global__ void __launch_bounds__(512, 1)
lstm_kernel(const float* __restrict__ x, const float* __restrict__ rnn_w,
            const float* __restrict__ rnn_b,
            float* __restrict__ hs, float* __restrict__ cs)
{
    extern __shared__ __align__(16) char dsm[];
    const uint32_t base_u = smem_u32(dsm);
    float* xs  = (float*)(dsm + L_XS);
    float* wx  = (float*)(dsm + L_WX);
    float* bs  = (float*)(dsm + L_BS);
    float* hst = (float*)(dsm + L_HST);
    float* cst = (float*)(dsm + L_CST);

    const int tid  = threadIdx.x;
    const int wid  = tid >> 5, lane = tid & 31;
    const int wm   = wid & 3,  wn   = wid >> 2;
    const int g    = lane >> 2, tg  = lane & 3;
    const int lr   = lane & 15, lc8 = (lane >> 4) << 3;
    const int cg   = blockIdx.x & 7;
    const int rt   = blockIdx.x >> 3;
    const int r0   = rt * 64;
    const int hu0  = cg * 16;

    // stage gate weights once (gate-interleaved c = u*4+q), bf16 hi/lo
    for (int i = tid; i < 128 * 64; i += 512) {
        const int k = i >> 6, c = i & 63;
        const int u = c >> 2, q = c & 3;
        __nv_bfloat16 hi, lo;
        split2(rnn_w[(size_t)(3 + k) * NGATE + q * NHD + hu0 + u], hi, lo);
        *(__nv_bfloat16*)(dsm + L_WHH + 2 * (k * SWH + c)) = hi;
        *(__nv_bfloat16*)(dsm + L_WHL + 2 * (k * SWH + c)) = lo;
    }
    if (tid < 192) {
        const int m = tid >> 6, c = tid & 63;
        const int u = c >> 2, q = c & 3;
        wx[m * 64 + c] = rnn_w[(size_t)m * NGATE + q * NHD + hu0 + u];
    }
    if (tid < 64) {
        const int u = tid >> 2, q = tid & 3;
        bs[tid] = rnn_b[q * NHD + hu0 + u];
    }

    // persistent cell state: even-tg lanes own (rows wm*16+g, wm*16+g+8) x unit
    const int rA = wm * 16 + g, rB = rA + 8;
    float creg[4];
    if (!(tg & 1)) {
#pragma unroll
        for (int nt = 0; nt < 2; nt++) {
            const int ul = (wn * 16 + nt * 8 + tg * 2) >> 2;
            creg[nt * 2]     = g_c0[(size_t)(r0 + rA) * NHD + hu0 + ul];
            creg[nt * 2 + 1] = g_c0[(size_t)(r0 + rB) * NHD + hu0 + ul];
        }
    }
    __syncthreads();

    for (int t = 0; t < TT; t++) {
        // stage A = h_{t-1} (pre-split, slot t): pure uint4 copies
        {
            const size_t sb = ((size_t)t * BB + r0) * NHD;
            for (int i = tid; i < 64 * 16; i += 512) {
                const int row = i >> 4, ch = i & 15;
                *(uint4*)(dsm + L_AHI + 2 * (row * SAH + ch * 8)) =
                    *(const uint4*)&g_hh[sb + (size_t)row * NHD + ch * 8];
                *(uint4*)(dsm + L_ALO + 2 * (row * SAH + ch * 8)) =
                    *(const uint4*)&g_hl[sb + (size_t)row * NHD + ch * 8];
            }
            if (tid < 192)
                xs[(tid / 3) * 4 + (tid % 3)] = x[((size_t)t * BB + r0) * 3 + tid];
        }
        __syncthreads();

        // gate MMA: 16x16 per warp, K=128, 4 split terms (exact product)
        float acc[2][4];
#pragma unroll
        for (int a = 0; a < 2; a++)
#pragma unroll
            for (int b = 0; b < 4; b++) acc[a][b] = 0.0f;

#pragma unroll
        for (int kc = 0; kc < 8; kc++) {
            const int k = kc * 16;
            uint32_t ah[4], al[4];
            const uint32_t aoff = 2 * ((wm * 16 + lr) * SAH + k + lc8);
            ldsm_x4(ah[0], ah[1], ah[2], ah[3], base_u + L_AHI + aoff);
            ldsm_x4(al[0], al[1], al[2], al[3], base_u + L_ALO + aoff);
            uint32_t bh[2][2], bl[2][2];
            const uint32_t boff = 2 * ((k + lr) * SWH + wn * 16 + lc8);
            ldsm_x4_t(bh[0][0], bh[0][1], bh[1][0], bh[1][1], base_u + L_WHH + boff);
            ldsm_x4_t(bl[0][0], bl[0][1], bl[1][0], bl[1][1], base_u + L_WHL + boff);
#pragma unroll
            for (int nt = 0; nt < 2; nt++) {
                mma16816(acc[nt], ah, bh[nt]);
                mma16816(acc[nt], ah, bl[nt]);
                mma16816(acc[nt], al, bh[nt]);
                mma16816(acc[nt], al, bl[nt]);
            }
        }

        // add bias + x contribution (fp32, exact)
        const float xa0 = xs[rA * 4], xa1 = xs[rA * 4 + 1], xa2 = xs[rA * 4 + 2];
        const float xb0 = xs[rB * 4], xb1 = xs[rB * 4 + 1], xb2 = xs[rB * 4 + 2];
#pragma unroll
        for (int nt = 0; nt < 2; nt++) {
            const int c0 = wn * 16 + nt * 8 + tg * 2;
#pragma unroll
            for (int cc = 0; cc < 2; cc++) {
                const int c = c0 + cc;
                const float w0 = wx[c], w1 = wx[64 + c], w2 = wx[128 + c], bb = bs[c];
                acc[nt][cc]     += bb + xa0 * w0 + xa1 * w1 + xa2 * w2;
                acc[nt][2 + cc] += bb + xb0 * w0 + xb1 * w1 + xb2 * w2;
            }
        }

        // gate exchange: even tg holds (i,j); partner (tg^1) holds (f,o)
#pragma unroll
        for (int nt = 0; nt < 2; nt++) {
            const float p0 = __shfl_xor_sync(0xffffffffu, acc[nt][0], 1);
            const float p1 = __shfl_xor_sync(0xffffffffu, acc[nt][1], 1);
            const float p2 = __shfl_xor_sync(0xffffffffu, acc[nt][2], 1);
            const float p3 = __shfl_xor_sync(0xffffffffu, acc[nt][3], 1);
            if (!(tg & 1)) {
                const int ul = (wn * 16 + nt * 8 + tg * 2) >> 2;
                const float cA = creg[nt * 2] * sigm(p0 + 1.0f)
                               + sigm(acc[nt][0]) * tanhf(acc[nt][1]);
                const float hA = tanhf(cA) * sigm(p1);
                const float cB = creg[nt * 2 + 1] * sigm(p2 + 1.0f)
                               + sigm(acc[nt][2]) * tanhf(acc[nt][3]);
                const float hB = tanhf(cB) * sigm(p3);
                creg[nt * 2] = cA;
                creg[nt * 2 + 1] = cB;
                hst[rA * SHT + ul] = hA;
                cst[rA * SHT + ul] = cA;
                hst[rB * SHT + ul] = hB;
                cst[rB * SHT + ul] = cB;
            }
        }
        __syncthreads();

        // coalesced outputs: hs/cs fp32 + g_hh/g_hl slot t+1 (bf16 split)
        if (tid < 256) {
            const int row = tid >> 2, q4 = tid & 3;
            const float4 hv = *(const float4*)&hst[row * SHT + q4 * 4];
            const float4 cv = *(const float4*)&cst[row * SHT + q4 * 4];
            const size_t go = ((size_t)t * BB + r0 + row) * NHD + hu0 + q4 * 4;
            *(float4*)&hs[go] = hv;
            *(float4*)&cs[go] = cv;
            __nv_bfloat16 h0b, l0b, h1b, l1b, h2b, l2b, h3b, l3b;
            split2(hv.x, h0b, l0b); split2(hv.y, h1b, l1b);
            split2(hv.z, h2b, l2b); split2(hv.w, h3b, l3b);
            const size_t gb = ((size_t)(t + 1) * BB + r0 + row) * NHD + hu0 + q4 * 4;
            __nv_bfloat162 p0; p0.x = h0b; p0.y = h1b;
            __nv_bfloat162 p1; p1.x = h2b; p1.y = h3b;
            __nv_bfloat162 q0; q0.x = l0b; q0.y = l1b;
            __nv_bfloat162 q1; q1.x = l2b; q1.y = l3b;
            *(__nv_bfloat162*)&g_hh[gb]     = p0;
            *(__nv_bfloat162*)&g_hh[gb + 2] = p1;
            *(__nv_bfloat162*)&g_hl[gb]     = q0;
            *(__nv_bfloat162*)&g_hl[gb + 2] = q1;
        }

        // per-row-tile barrier (8 blocks)
        __threadfence();
        __syncthreads();
        if (tid == 0) {
            const unsigned gen = g_gen16[rt];
            if (atomicAdd(&g_cnt16[rt], 1u) == 7u) {
                g_cnt16[rt] = 0u;
                __threadfence();
                g_gen16[rt] = gen + 1u;
            } else {
                while (g_gen16[rt] == gen) { }
            }
        }
        __syncthreads();
    }
}

// ---------------------------------------------------------------------------
// HMMA GEMM chunk: block tile M128 x N128, K=128, 512 threads (16 warps, 4x4).
// All operands pre-split bf16 hi/lo in global — staging is pure uint4 copies.
// ---------------------------------------------------------------------------
#define SRA  136
#define A_HI 0u
#define A_LO 34816u
#define B_HI 69632u
#define B_LO 104448u
#define MM_SMEM 139264u

__device__ __forceinline__ void mma_chunk_bf16(
    const __nv_bfloat16* __restrict__ gAh, const __nv_bfloat16* __restrict__ gAl, int lda,
    const __nv_bfloat16* __restrict__ gBh, const __nv_bfloat16* __restrict__ gBl, int ldb,
    char* dsm, uint32_t base_u, float (&acc)[2][4][4])
{
    const int tid = threadIdx.x;
    const int wid = tid >> 5, lane = tid & 31;
    const int wm = wid & 3, wn = wid >> 2;
    const int lr = lane & 15, lc8 = (lane >> 4) << 3;

    __syncthreads();
    for (int i = tid; i < 128 * 16; i += 512) {
        const int row = i >> 4, ch = i & 15;
        *(uint4*)(dsm + A_HI + 2 * (row * SRA + ch * 8)) =
            *(const uint4*)&gAh[(size_t)row * lda + ch * 8];
        *(uint4*)(dsm + A_LO + 2 * (row * SRA + ch * 8)) =
            *(const uint4*)&gAl[(size_t)row * lda + ch * 8];
        *(uint4*)(dsm + B_HI + 2 * (row * SRA + ch * 8)) =
            *(const uint4*)&gBh[(size_t)row * ldb + ch * 8];
        *(uint4*)(dsm + B_LO + 2 * (row * SRA + ch * 8)) =
            *(const uint4*)&gBl[(size_t)row * ldb + ch * 8];
    }
    __syncthreads();

#pragma unroll
    for (int kc = 0; kc < 8; kc++) {
        const int k = kc * 16;
        uint32_t ah[2][4], al[2][4];
#pragma unroll
        for (int mt = 0; mt < 2; mt++) {
            const uint32_t aoff = 2 * ((wm * 32 + mt * 16 + lr) * SRA + k + lc8);
            ldsm_x4(ah[mt][0], ah[mt][1], ah[mt][2], ah[mt][3], base_u + A_HI + aoff);
            ldsm_x4(al[mt][0], al[mt][1], al[mt][2], al[mt][3], base_u + A_LO + aoff);
        }
        uint32_t bh[4][2], bl[4][2];
#pragma unroll
        for (int p = 0; p < 2; p++) {
            const uint32_t boff = 2 * ((k + lr) * SRA + wn * 32 + p * 16 + lc8);
            ldsm_x4_t(bh[2*p][0], bh[2*p][1], bh[2*p+1][0], bh[2*p+1][1], base_u + B_HI + boff);
            ldsm_x4_t(bl[2*p][0], bl[2*p][1], bl[2*p+1][0], bl[2*p+1][1], base_u + B_LO + boff);
        }
#pragma unroll
        for (int mt = 0; mt < 2; mt++)
#pragma unroll
            for (int nt = 0; nt < 4; nt++) {
                mma16816(acc[mt][nt], ah[mt], bh[nt]);
                mma16816(acc[mt][nt], ah[mt], bl[nt]);
                mma16816(acc[mt][nt], al[mt], bh[nt]);
            }
    }
}

// bn = hs @ bneck_w  -> fp32 bn_out + bf16 split g_bnh/g_bnl
__global__ void __launch_bounds__(512, 1)
bn_kernel(float* __restrict__ bn_out)
{
    extern __shared__ __align__(16) char dsm[];
    const uint32_t base_u = smem_u32(dsm);
    const int tid = threadIdx.x;
    const int wid = tid >> 5, lane = tid & 31;
    const int wm = wid & 3, wn = wid >> 2;
    const int g = lane >> 2, tg2 = (lane & 3) * 2;
    const int m0 = blockIdx.x * 128, nh = blockIdx.y;

    float acc[2][4][4];
#pragma unroll
    for (int a = 0; a < 2; a++)
#pragma unroll
        for (int b = 0; b < 4; b++)
#pragma unroll
            for (int c = 0; c < 4; c++) acc[a][b][c] = 0.0f;

    // h slots 1..TT
    mma_chunk_bf16(g_hh + (size_t)(BB + m0) * NHD, g_hl + (size_t)(BB + m0) * NHD, NHD,
                   g_bwh + nh * 128, g_bwl + nh * 128, NBOT, dsm, base_u, acc);

#pragma unroll
    for (int mt = 0; mt < 2; mt++)
#pragma unroll
    for (int nt = 0; nt < 4; nt++) {
        const int row = m0 + wm * 32 + mt * 16 + g;
        const int col = nh * 128 + wn * 32 + nt * 8 + tg2;
        const float* a4 = acc[mt][nt];
        *(float2*)&bn_out[(size_t)row * 256 + col]       = make_float2(a4[0], a4[1]);
        *(float2*)&bn_out[(size_t)(row + 8) * 256 + col] = make_float2(a4[2], a4[3]);
        __nv_bfloat16 h0b, l0b, h1b, l1b;
        __nv_bfloat162 ph, pl;
        split2(a4[0], h0b, l0b); split2(a4[1], h1b, l1b);
        ph.x = h0b; ph.y = h1b; pl.x = l0b; pl.y = l1b;
        *(__nv_bfloat162*)&g_bnh[(size_t)row * 256 + col] = ph;
        *(__nv_bfloat162*)&g_bnl[(size_t)row * 256 + col] = pl;
        split2(a4[2], h0b, l0b); split2(a4[3], h1b, l1b);
        ph.x = h0b; ph.y = h1b; pl.x = l0b; pl.y = l1b;
        *(__nv_bfloat162*)&g_bnh[(size_t)(row + 8) * 256 + col] = ph;
        *(__nv_bfloat162*)&g_bnl[(size_t)(row + 8) * 256 + col] = pl;
    }
}

// pc = bn @ pc_w + pc_b   (K=256: two chunks)
__global__ void __launch_bounds__(512, 1)
pc_kernel(const float* __restrict__ pc_b, float* __restrict__ pc_out)
{
    extern __shared__ __align__(16) char dsm[];
    const uint32_t base_u = smem_u32(dsm);
    const int tid = threadIdx.x;
    const int wid = tid >> 5, lane = tid & 31;
    const int wm = wid & 3, wn = wid >> 2;
    const int g = lane >> 2, tg2 = (lane & 3) * 2;
    const int m0 = blockIdx.x * 128, nh = blockIdx.y;

    float acc[2][4][4];
#pragma unroll
    for (int a = 0; a < 2; a++)
#pragma unroll
        for (int b = 0; b < 4; b++)
#pragma unroll
            for (int c = 0; c < 4; c++) acc[a][b][c] = 0.0f;

#pragma unroll 1
    for (int kc = 0; kc < 2; kc++)
        mma_chunk_bf16(g_bnh + (size_t)m0 * NBOT + kc * 128,
                       g_bnl + (size_t)m0 * NBOT + kc * 128, NBOT,
                       g_pwh + (size_t)kc * 128 * NPC + nh * 128,
                       g_pwl + (size_t)kc * 128 * NPC + nh * 128, NPC,
                       dsm, base_u, acc);

#pragma unroll
    for (int mt = 0; mt < 2; mt++)
#pragma unroll
    for (int nt = 0; nt < 4; nt++) {
        const int row = m0 + wm * 32 + mt * 16 + g;
        const int col = nh * 128 + wn * 32 + nt * 8 + tg2;
        const float b0 = __ldg(&pc_b[col]), b1 = __ldg(&pc_b[col + 1]);
        const float* a4 = acc[mt][nt];
        *(float2*)&pc_out[(size_t)row * 256 + col] = make_float2(a4[0] + b0, a4[1] + b1);
        *(float2*)&pc_out[(size_t)(row + 8) * 256 + col] = make_float2(a4[2] + b0, a4[3] + b1);
    }
}

// hd = bn @ hd_w + hd_b  (fp32)
__global__ void __launch_bounds__(256, 1)
hd_kernel(const float* __restrict__ bn, const float* __restrict__ hd_w,
          const float* __restrict__ hd_b, float* __restrict__ hd_out)
{
    __shared__ float bn_s[32 * 257];
    __shared__ float w_s[256 * 12];
    const int tid = threadIdx.x;
    const int m0 = blockIdx.x * 32;

    for (int i = tid; i < 32 * 256; i += 256) {
        const int row = i >> 8, k = i & 255;
        bn_s[row * 257 + k] = bn[(size_t)(m0 + row) * 256 + k];
    }
    for (int i = tid; i < 256 * 12; i += 256) w_s[i] = hd_w[i];
    __syncthreads();

#pragma unroll
    for (int p = 0; p < 2; p++) {
        const int o = tid + p * 256;
        if (o < 384) {
            const int row = o / 12, n = o % 12;
            float s = hd_b[n];
            const float* br = &bn_s[row * 257];
#pragma unroll 8
            for (int k = 0; k < 256; k++) s = fmaf(br[k], w_s[k * 12 + n], s);
            hd_out[(size_t)(m0 + row) * 12 + n] = s;
        }
    }
}

// ---------------------------------------------------------------------------
extern "C" void kernel_launch(void* const* d_in, const int* in_sizes, int n_in,
                              void* d_out, int out_size)
{
    const float* x       = (const float*)d_in[0];
    const float* init    = (const float*)d_in[1];
    const float* rnn_w   = (const float*)d_in[2];
    const float* rnn_b   = (const float*)d_in[3];
    const float* state_w = (const float*)d_in[4];
    const float* state_b = (const float*)d_in[5];
    const float* cell_w  = (const float*)d_in[6];
    const float* cell_b  = (const float*)d_in[7];
    const float* bneck_w = (const float*)d_in[8];
    const float* pc_w    = (const float*)d_in[9];
    const float* pc_b    = (const float*)d_in[10];
    const float* hd_w    = (const float*)d_in[11];
    const float* hd_b    = (const float*)d_in[12];

    float* out = (float*)d_out;
    float* hd_out = out;
    float* pc_out = hd_out + (size_t)TB * NHDC;
    float* bn_out = pc_out + (size_t)TB * NPC;
    float* hs_out = bn_out + (size_t)TB * NBOT;
    float* cs_out = hs_out + (size_t)TB * NHD;

    float* c0p = nullptr;
    cudaGetSymbolAddress((void**)&c0p, g_c0);
    __nv_bfloat16 *hhp = nullptr, *hlp = nullptr;
    cudaGetSymbolAddress((void**)&hhp, g_hh);
    cudaGetSymbolAddress((void**)&hlp, g_hl);
    // h0 fp32 target: reuse hs_out slot? No — write fp32 h0 into cs_out temp is
    // unsafe. Use a dedicated scratch: overwrite later. We only need split h0,
    // but gemm also wants a fp32 C; point it at bn_out (overwritten by bn later).
    float* h0tmp = bn_out;

    cudaFuncSetAttribute(lstm_kernel, cudaFuncAttributeMaxDynamicSharedMemorySize, LSTM_SMEM);
    cudaFuncSetAttribute(bn_kernel, cudaFuncAttributeMaxDynamicSharedMemorySize, MM_SMEM);
    cudaFuncSetAttribute(pc_kernel, cudaFuncAttributeMaxDynamicSharedMemorySize, MM_SMEM);

    // h0 (split into g_hh/g_hl slot 0), c0
    gemm_kernel<<<dim3(2, 16), 256>>>(init, state_w, state_b, h0tmp, hhp, hlp, BB, NHD, NIC);
    gemm_kernel<<<dim3(2, 16), 256>>>(init, cell_w, cell_b, c0p, nullptr, nullptr, BB, NHD, NIC);
    split_w_kernel<<<(NHD * NBOT + NBOT * NPC + 255) / 256, 256>>>(bneck_w, pc_w);

    lstm_kernel<<<128, 512, LSTM_SMEM>>>(x, rnn_w, rnn_b, hs_out, cs_out);

    bn_kernel<<<dim3(TB / 128, 2), 512, MM_SMEM>>>(bn_out);
    pc_kernel<<<dim3(TB / 128, 2), 512, MM_SMEM>>>(pc_b, pc_out);
    hd_kernel<<<TB / 32, 256>>>(bn_out, hd_w, hd_b, hd_out);
}

// round 8
// speedup vs baseline: 2.1555x; 1.0264x over previous
#include <cuda_runtime.h>
#include <cuda_bf16.h>
#include <cstdint>
#include <cstddef>

#define TT   100
#define BB   1024
#define NHD  128
#define NGATE 512
#define NIC  268
#define NBOT 256
#define NPC  256
#define NHDC 12
#define TB   (TT * BB)

// ---------------------------------------------------------------------------
// device scratch
// ---------------------------------------------------------------------------
__device__ float g_c0[BB * NHD];
// h history pre-split bf16: slot 0 = h0, slot t+1 = h_t
__device__ __nv_bfloat16 g_hh[(size_t)(TT + 1) * BB * NHD];
__device__ __nv_bfloat16 g_hl[(size_t)(TT + 1) * BB * NHD];
__device__ __nv_bfloat16 g_bwh[NHD * NBOT], g_bwl[NHD * NBOT];
__device__ __nv_bfloat16 g_pwh[NBOT * NPC], g_pwl[NBOT * NPC];
__device__ __nv_bfloat16 g_hdh[NBOT * 16], g_hdl[NBOT * 16];   // hd_w padded N16
// per-32-row-tile flags: g_flag[rt*32 + cg], monotonically increasing epochs
__device__ unsigned g_flag[32 * 32];

__device__ __forceinline__ float sigm(float v) { return 1.0f / (1.0f + __expf(-v)); }
__device__ __forceinline__ float tanh_fast(float v) {
    return 1.0f - 2.0f / (__expf(2.0f * v) + 1.0f);
}
__device__ __forceinline__ void split2(float v, __nv_bfloat16& hi, __nv_bfloat16& lo) {
    hi = __float2bfloat16(v);
    lo = __float2bfloat16(v - __bfloat162float(hi));
}
__device__ __forceinline__ uint32_t smem_u32(const void* p) {
    uint32_t a;
    asm("{ .reg .u64 t; cvta.to.shared.u64 t, %1; cvt.u32.u64 %0, t; }" : "=r"(a) : "l"(p));
    return a;
}
__device__ __forceinline__ void ldsm_x4(uint32_t& r0, uint32_t& r1, uint32_t& r2,
                                        uint32_t& r3, uint32_t addr) {
    asm volatile("ldmatrix.sync.aligned.m8n8.x4.shared.b16 {%0,%1,%2,%3}, [%4];"
                 : "=r"(r0), "=r"(r1), "=r"(r2), "=r"(r3) : "r"(addr));
}
__device__ __forceinline__ void ldsm_x4_t(uint32_t& r0, uint32_t& r1, uint32_t& r2,
                                          uint32_t& r3, uint32_t addr) {
    asm volatile("ldmatrix.sync.aligned.m8n8.x4.trans.shared.b16 {%0,%1,%2,%3}, [%4];"
                 : "=r"(r0), "=r"(r1), "=r"(r2), "=r"(r3) : "r"(addr));
}
__device__ __forceinline__ void mma16816(float* d, const uint32_t* a, const uint32_t* b) {
    asm volatile(
        "mma.sync.aligned.m16n8k16.row.col.f32.bf16.bf16.f32 "
        "{%0,%1,%2,%3}, {%4,%5,%6,%7}, {%8,%9}, {%0,%1,%2,%3};"
        : "+f"(d[0]), "+f"(d[1]), "+f"(d[2]), "+f"(d[3])
        : "r"(a[0]), "r"(a[1]), "r"(a[2]), "r"(a[3]), "r"(b[0]), "r"(b[1]));
}
__device__ __forceinline__ void bar_grp(int wg) {
    if (wg == 0) asm volatile("bar.sync 1, 256;" ::: "memory");
    else         asm volatile("bar.sync 2, 256;" ::: "memory");
}

// ---------------------------------------------------------------------------
// weight pre-split (bneck_w, pc_w, hd_w padded to N16)
// ---------------------------------------------------------------------------
__global__ void split_w_kernel(const float* __restrict__ bw, const float* __restrict__ pw,
                               const float* __restrict__ hw)
{
    const int i = blockIdx.x * 256 + threadIdx.x;
    __nv_bfloat16 hi, lo;
    if (i < NHD * NBOT) {
        split2(bw[i], hi, lo);
        g_bwh[i] = hi; g_bwl[i] = lo;
    } else if (i < NHD * NBOT + NBOT * NPC) {
        const int j = i - NHD * NBOT;
        split2(pw[j], hi, lo);
        g_pwh[j] = hi; g_pwl[j] = lo;
    } else if (i < NHD * NBOT + NBOT * NPC + NBOT * 16) {
        const int j = i - NHD * NBOT - NBOT * NPC;
        const int k = j >> 4, n = j & 15;
        split2((n < 12) ? hw[k * 12 + n] : 0.0f, hi, lo);
        g_hdh[j] = hi; g_hdl[j] = lo;
    }
}

// ---------------------------------------------------------------------------
// fp32 GEMM for h0/c0 init; optional bf16 hi/lo emission (h0 -> slot 0)
// ---------------------------------------------------------------------------
__global__ void gemm_kernel(const float* __restrict__ A, const float* __restrict__ W,
                            const float* __restrict__ bias, float* __restrict__ C,
                            __nv_bfloat16* __restrict__ oh, __nv_bfloat16* __restrict__ ol,
                            int M, int N, int K)
{
    __shared__ float As[16][68];
    __shared__ float Ws[16][68];
    const int tid = threadIdx.x;
    const int tx = tid & 15, ty = tid >> 4;
    const int n0 = blockIdx.x * 64, m0 = blockIdx.y * 64;

    float acc[4][4];
#pragma unroll
    for (int r = 0; r < 4; r++)
#pragma unroll
        for (int q = 0; q < 4; q++) acc[r][q] = 0.0f;

    for (int k0 = 0; k0 < K; k0 += 16) {
        {
            const int k = tid & 15, m = tid >> 4;
#pragma unroll
            for (int p = 0; p < 4; p++) {
                const int mm = m + p * 16;
                float v = 0.0f;
                if (k0 + k < K) v = A[(size_t)(m0 + mm) * K + (k0 + k)];
                As[k][mm] = v;
            }
        }
        {
            const int n = tid & 63, kb = tid >> 6;
#pragma unroll
            for (int p = 0; p < 4; p++) {
                const int kk = kb + p * 4;
                float v = 0.0f;
                if ((k0 + kk < K) && (n0 + n < N)) v = W[(size_t)(k0 + kk) * N + (n0 + n)];
                Ws[kk][n] = v;
            }
        }
        __syncthreads();
#pragma unroll
        for (int kk = 0; kk < 16; kk++) {
            const float4 a4 = *(const float4*)&As[kk][ty * 4];
            const float4 b4 = *(const float4*)&Ws[kk][tx * 4];
            const float av[4] = {a4.x, a4.y, a4.z, a4.w};
            const float bv[4] = {b4.x, b4.y, b4.z, b4.w};
#pragma unroll
            for (int r = 0; r < 4; r++)
#pragma unroll
                for (int q = 0; q < 4; q++)
                    acc[r][q] = fmaf(av[r], bv[q], acc[r][q]);
        }
        __syncthreads();
    }
#pragma unroll
    for (int r = 0; r < 4; r++) {
        const int m = m0 + ty * 4 + r;
#pragma unroll
        for (int q = 0; q < 4; q++) {
            const int n = n0 + tx * 4 + q;
            if (n < N) {
                const float v = acc[r][q] + (bias ? bias[n] : 0.0f);
                C[(size_t)m * N + n] = v;
                if (oh) {
                    __nv_bfloat16 hi, lo;
                    split2(v, hi, lo);
                    oh[(size_t)m * N + n] = hi;
                    ol[(size_t)m * N + n] = lo;
                }
            }
        }
    }
}

// ---------------------------------------------------------------------------
// LSTM recurrence: 128 blocks x 512 threads. Each block = TWO independent
// warp-groups (warps 0-7 / 8-15), each owning 32 rows x 16 units, syncing
// with 7 peer blocks via per-row-tile flags + named barriers. The two
// chains drift freely and hide each other's L2/flag latency.
// ---------------------------------------------------------------------------
#define L_WHH 0u              // [128][72] bf16
#define L_WHL 18432u
#define L_A(g)   (36864u + (g) * 17408u)   // hi [32][136] bf16; lo at +8704
#define L_XS(g)  (71680u + (g) * 512u)     // [32][4] f32
#define L_WX  72704u                        // [3][64] f32
#define L_BS  73472u                        // [64] f32
#define L_HST(g) (73728u + (g) * 5120u)    // [32][20] f32; cst at +2560
#define LSTM_SMEM 83968u
#define SWH 72
#define SAH 136
#define SHT 20

__global__ void __launch_bounds__(512, 1)
lstm_kernel(const float* __restrict__ x, const float* __restrict__ rnn_w,
            const float* __restrict__ rnn_b,
            float* __restrict__ hs, float* __restrict__ cs)
{
    extern __shared__ __align__(16) char dsm[];
    const uint32_t base_u = smem_u32(dsm);
    __shared__ unsigned s_base;

    const int tid  = threadIdx.x;
    const int wg   = tid >> 8;          // warpgroup 0/1
    const int wtid = tid & 255;
    const int gw   = wtid >> 5;         // warp in group 0..7
    const int lane = tid & 31;
    const int wm   = gw & 1,  wn = gw >> 1;
    const int g    = lane >> 2, tg = lane & 3;
    const int lr   = lane & 15, lc8 = (lane >> 4) << 3;
    const int cg   = blockIdx.x & 7;
    const int rp   = blockIdx.x >> 3;
    const int hu0  = cg * 16;
    const int r0g  = rp * 64 + wg * 32;
    const int rtf  = rp * 2 + wg;

    float* xs  = (float*)(dsm + L_XS(wg));
    float* wx  = (float*)(dsm + L_WX);
    float* bs  = (float*)(dsm + L_BS);
    float* hst = (float*)(dsm + L_HST(wg));
    float* cst = (float*)(dsm + L_HST(wg) + 2560u);
    const uint32_t AHI = L_A(wg), ALO = AHI + 8704u;

    // stage gate weights once (block-wide), bf16 hi/lo, cols c = u*4+q
    for (int i = tid; i < 128 * 64; i += 512) {
        const int k = i >> 6, c = i & 63;
        const int u = c >> 2, q = c & 3;
        __nv_bfloat16 hi, lo;
        split2(rnn_w[(size_t)(3 + k) * NGATE + q * NHD + hu0 + u], hi, lo);
        *(__nv_bfloat16*)(dsm + L_WHH + 2 * (k * SWH + c)) = hi;
        *(__nv_bfloat16*)(dsm + L_WHL + 2 * (k * SWH + c)) = lo;
    }
    if (tid < 192) {
        const int m = tid >> 6, c = tid & 63;
        const int u = c >> 2, q = c & 3;
        wx[m * 64 + c] = rnn_w[(size_t)m * NGATE + q * NHD + hu0 + u];
    }
    if (tid < 64) {
        const int u = tid >> 2, q = tid & 3;
        bs[tid] = rnn_b[q * NHD + hu0 + u];
    }
    if (tid == 0) s_base = *(volatile unsigned*)&g_flag[(rp * 2) * 32 + cg];

    // persistent cell state (even-tg lanes): rows rA/rB x 2 units
    const int rA = wm * 16 + g, rB = rA + 8;
    float creg[4];
    if (!(tg & 1)) {
#pragma unroll
        for (int nt = 0; nt < 2; nt++) {
            const int ul = (wn * 16 + nt * 8 + tg * 2) >> 2;
            creg[nt * 2]     = g_c0[(size_t)(r0g + rA) * NHD + hu0 + ul];
            creg[nt * 2 + 1] = g_c0[(size_t)(r0g + rB) * NHD + hu0 + ul];
        }
    }
    __syncthreads();
    const unsigned base = s_base;

    for (int t = 0; t < TT; t++) {
        // wait for the 7 peer blocks of this row tile (epoch-relative)
        if (gw == 0) {
            if (t > 0 && lane < 8 && lane != cg) {
                const unsigned tgt = base + (unsigned)t;
                while (*(volatile unsigned*)&g_flag[rtf * 32 + lane] < tgt) { }
            }
            __syncwarp();
        }
        bar_grp(wg);

        // stage A = h_{t-1} (slot t, pre-split) + x
        {
            const size_t sb = ((size_t)t * BB + r0g) * NHD;
            for (int i = wtid; i < 32 * 16; i += 256) {
                const int row = i >> 4, ch = i & 15;
                *(uint4*)(dsm + AHI + 2 * (row * SAH + ch * 8)) =
                    *(const uint4*)&g_hh[sb + (size_t)row * NHD + ch * 8];
                *(uint4*)(dsm + ALO + 2 * (row * SAH + ch * 8)) =
                    *(const uint4*)&g_hl[sb + (size_t)row * NHD + ch * 8];
            }
            if (wtid < 96)
                xs[(wtid / 3) * 4 + (wtid % 3)] = x[((size_t)t * BB + r0g) * 3 + wtid];
        }
        bar_grp(wg);

        // gate MMA: warp tile 16x16, K=128, 4 split terms (exact product)
        float acc[2][4];
#pragma unroll
        for (int a = 0; a < 2; a++)
#pragma unroll
            for (int b = 0; b < 4; b++) acc[a][b] = 0.0f;

#pragma unroll
        for (int kc = 0; kc < 8; kc++) {
            const int k = kc * 16;
            uint32_t ah[4], al[4];
            const uint32_t aoff = 2 * ((wm * 16 + lr) * SAH + k + lc8);
            ldsm_x4(ah[0], ah[1], ah[2], ah[3], base_u + AHI + aoff);
            ldsm_x4(al[0], al[1], al[2], al[3], base_u + ALO + aoff);
            uint32_t bh[2][2], bl[2][2];
            const uint32_t boff = 2 * ((k + lr) * SWH + wn * 16 + lc8);
            ldsm_x4_t(bh[0][0], bh[0][1], bh[1][0], bh[1][1], base_u + L_WHH + boff);
            ldsm_x4_t(bl[0][0], bl[0][1], bl[1][0], bl[1][1], base_u + L_WHL + boff);
#pragma unroll
            for (int nt = 0; nt < 2; nt++) {
                mma16816(acc[nt], ah, bh[nt]);
                mma16816(acc[nt], ah, bl[nt]);
                mma16816(acc[nt], al, bh[nt]);
                mma16816(acc[nt], al, bl[nt]);
            }
        }

        // bias + x contribution (fp32 exact)
        const float xa0 = xs[rA * 4], xa1 = xs[rA * 4 + 1], xa2 = xs[rA * 4 + 2];
        const float xb0 = xs[rB * 4], xb1 = xs[rB * 4 + 1], xb2 = xs[rB * 4 + 2];
#pragma unroll
        for (int nt = 0; nt < 2; nt++) {
            const int c0 = wn * 16 + nt * 8 + tg * 2;
#pragma unroll
            for (int cc = 0; cc < 2; cc++) {
                const int c = c0 + cc;
                const float w0 = wx[c], w1 = wx[64 + c], w2 = wx[128 + c], bb = bs[c];
                acc[nt][cc]     += bb + xa0 * w0 + xa1 * w1 + xa2 * w2;
                acc[nt][2 + cc] += bb + xb0 * w0 + xb1 * w1 + xb2 * w2;
            }
        }

        // gate exchange + cell update (even tg owns; partner has f,o)
#pragma unroll
        for (int nt = 0; nt < 2; nt++) {
            const float p0 = __shfl_xor_sync(0xffffffffu, acc[nt][0], 1);
            const float p1 = __shfl_xor_sync(0xffffffffu, acc[nt][1], 1);
            const float p2 = __shfl_xor_sync(0xffffffffu, acc[nt][2], 1);
            const float p3 = __shfl_xor_sync(0xffffffffu, acc[nt][3], 1);
            if (!(tg & 1)) {
                const int ul = (wn * 16 + nt * 8 + tg * 2) >> 2;
                const float cA = creg[nt * 2] * sigm(p0 + 1.0f)
                               + sigm(acc[nt][0]) * tanh_fast(acc[nt][1]);
                const float hA = tanh_fast(cA) * sigm(p1);
                const float cB = creg[nt * 2 + 1] * sigm(p2 + 1.0f)
                               + sigm(acc[nt][2]) * tanh_fast(acc[nt][3]);
                const float hB = tanh_fast(cB) * sigm(p3);
                creg[nt * 2] = cA;
                creg[nt * 2 + 1] = cB;
                hst[rA * SHT + ul] = hA;
                cst[rA * SHT + ul] = cA;
                hst[rB * SHT + ul] = hB;
                cst[rB * SHT + ul] = cB;
            }
        }
        bar_grp(wg);

        // outputs: hs/cs fp32 + g_hh/g_hl slot t+1 (bf16 split), coalesced
        if (wtid < 128) {
            const int row = wtid >> 2, q4 = wtid & 3;
            const float4 hv = *(const float4*)&hst[row * SHT + q4 * 4];
            const float4 cv = *(const float4*)&cst[row * SHT + q4 * 4];
            const size_t go = ((size_t)t * BB + r0g + row) * NHD + hu0 + q4 * 4;
            *(float4*)&hs[go] = hv;
            *(float4*)&cs[go] = cv;
            __nv_bfloat16 h0b, l0b, h1b, l1b, h2b, l2b, h3b, l3b;
            split2(hv.x, h0b, l0b); split2(hv.y, h1b, l1b);
            split2(hv.z, h2b, l2b); split2(hv.w, h3b, l3b);
            const size_t gb = ((size_t)(t + 1) * BB + r0g + row) * NHD + hu0 + q4 * 4;
            __nv_bfloat162 p0; p0.x = h0b; p0.y = h1b;
            __nv_bfloat162 p1; p1.x = h2b; p1.y = h3b;
            __nv_bfloat162 q0; q0.x = l0b; q0.y = l1b;
            __nv_bfloat162 q1; q1.x = l2b; q1.y = l3b;
            *(__nv_bfloat162*)&g_hh[gb]     = p0;
            *(__nv_bfloat162*)&g_hh[gb + 2] = p1;
            *(__nv_bfloat162*)&g_hl[gb]     = q0;
            *(__nv_bfloat162*)&g_hl[gb + 2] = q1;
        }

        if (t < TT - 1) {
            __threadfence();
            bar_grp(wg);
            if (wtid == 0)
                *(volatile unsigned*)&g_flag[rtf * 32 + cg] = base + (unsigned)t + 1u;
        }
    }
}

// ---------------------------------------------------------------------------
// bn = hs @ bneck_w  (fp32 out only). Block 128x128, 512 threads.
// ---------------------------------------------------------------------------
#define SRA  136
#define A_HI 0u
#define A_LO 34816u
#define B_HI 69632u
#define B_LO 104448u
#define MM_SMEM 139264u

__global__ void __launch_bounds__(512, 1)
bn_kernel(float* __restrict__ bn_out)
{
    extern __shared__ __align__(16) char dsm[];
    const uint32_t base_u = smem_u32(dsm);
    const int tid = threadIdx.x;
    const int wid = tid >> 5, lane = tid & 31;
    const int wm = wid & 3, wn = wid >> 2;
    const int g = lane >> 2, tg2 = (lane & 3) * 2;
    const int lr = lane & 15, lc8 = (lane >> 4) << 3;
    const int m0 = blockIdx.x * 128, nh = blockIdx.y;

    // stage A (h slots 1..TT) + B (pre-split)
    for (int i = tid; i < 128 * 16; i += 512) {
        const int row = i >> 4, ch = i & 15;
        *(uint4*)(dsm + A_HI + 2 * (row * SRA + ch * 8)) =
            *(const uint4*)&g_hh[((size_t)BB + m0 + row) * NHD + ch * 8];
        *(uint4*)(dsm + A_LO + 2 * (row * SRA + ch * 8)) =
            *(const uint4*)&g_hl[((size_t)BB + m0 + row) * NHD + ch * 8];
        *(uint4*)(dsm + B_HI + 2 * (row * SRA + ch * 8)) =
            *(const uint4*)&g_bwh[(size_t)row * NBOT + nh * 128 + ch * 8];
        *(uint4*)(dsm + B_LO + 2 * (row * SRA + ch * 8)) =
            *(const uint4*)&g_bwl[(size_t)row * NBOT + nh * 128 + ch * 8];
    }
    __syncthreads();

    float acc[2][4][4];
#pragma unroll
    for (int a = 0; a < 2; a++)
#pragma unroll
        for (int b = 0; b < 4; b++)
#pragma unroll
            for (int c = 0; c < 4; c++) acc[a][b][c] = 0.0f;

#pragma unroll
    for (int kc = 0; kc < 8; kc++) {
        const int k = kc * 16;
        uint32_t ah[2][4], al[2][4];
#pragma unroll
        for (int mt = 0; mt < 2; mt++) {
            const uint32_t aoff = 2 * ((wm * 32 + mt * 16 + lr) * SRA + k + lc8);
            ldsm_x4(ah[mt][0], ah[mt][1], ah[mt][2], ah[mt][3], base_u + A_HI + aoff);
            ldsm_x4(al[mt][0], al[mt][1], al[mt][2], al[mt][3], base_u + A_LO + aoff);
        }
        uint32_t bh[4][2], bl[4][2];
#pragma unroll
        for (int p = 0; p < 2; p++) {
            const uint32_t boff = 2 * ((k + lr) * SRA + wn * 32 + p * 16 + lc8);
            ldsm_x4_t(bh[2*p][0], bh[2*p][1], bh[2*p+1][0], bh[2*p+1][1], base_u + B_HI + boff);
            ldsm_x4_t(bl[2*p][0], bl[2*p][1], bl[2*p+1][0], bl[2*p+1][1], base_u + B_LO + boff);
        }
#pragma unroll
        for (int mt = 0; mt < 2; mt++)
#pragma unroll
            for (int nt = 0; nt < 4; nt++) {
                mma16816(acc[mt][nt], ah[mt], bh[nt]);
                mma16816(acc[mt][nt], ah[mt], bl[nt]);
                mma16816(acc[mt][nt], al[mt], bh[nt]);
            }
    }

#pragma unroll
    for (int mt = 0; mt < 2; mt++)
#pragma unroll
    for (int nt = 0; nt < 4; nt++) {
        const int row = m0 + wm * 32 + mt * 16 + g;
        const int col = nh * 128 + wn * 32 + nt * 8 + tg2;
        const float* a4 = acc[mt][nt];
        *(float2*)&bn_out[(size_t)row * 256 + col]       = make_float2(a4[0], a4[1]);
        *(float2*)&bn_out[(size_t)(row + 8) * 256 + col] = make_float2(a4[2], a4[3]);
    }
}

// ---------------------------------------------------------------------------
// pc = bn @ pc_w + pc_b  (A split inline from bn fp32) with fused
// hd = bn @ hd_w + hd_b  (HMMA N=16 padded, warps 0-7 on nh==0 blocks)
// ---------------------------------------------------------------------------
#define P_HHI 139264u      // hd B chunk [128][24] bf16
#define P_HLO 145408u
#define PC_SMEM 151552u
#define SHD 24

__global__ void __launch_bounds__(512, 1)
pc_kernel(const float* __restrict__ bn, const float* __restrict__ pc_b,
          const float* __restrict__ hd_b,
          float* __restrict__ pc_out, float* __restrict__ hd_out)
{
    extern __shared__ __align__(16) char dsm[];
    const uint32_t base_u = smem_u32(dsm);
    const int tid = threadIdx.x;
    const int wid = tid >> 5, lane = tid & 31;
    const int wm = wid & 3, wn = wid >> 2;
    const int g = lane >> 2, tg2 = (lane & 3) * 2;
    const int lr = lane & 15, lc8 = (lane >> 4) << 3;
    const int m0 = blockIdx.x * 128, nh = blockIdx.y;
    const bool do_hd = (nh == 0) && (wid < 8);

    float acc[2][4][4];
#pragma unroll
    for (int a = 0; a < 2; a++)
#pragma unroll
        for (int b = 0; b < 4; b++)
#pragma unroll
            for (int c = 0; c < 4; c++) acc[a][b][c] = 0.0f;
    float hacc[2][4];
#pragma unroll
    for (int a = 0; a < 2; a++)
#pragma unroll
        for (int b = 0; b < 4; b++) hacc[a][b] = 0.0f;

#pragma unroll 1
    for (int kc = 0; kc < 2; kc++) {
        __syncthreads();
        // stage A: bn fp32 -> split bf16 hi/lo
        for (int i = tid; i < 128 * 128; i += 512) {
            const int row = i >> 7, k = i & 127;
            __nv_bfloat16 hi, lo;
            split2(bn[(size_t)(m0 + row) * 256 + kc * 128 + k], hi, lo);
            *(__nv_bfloat16*)(dsm + A_HI + 2 * (row * SRA + k)) = hi;
            *(__nv_bfloat16*)(dsm + A_LO + 2 * (row * SRA + k)) = lo;
        }
        // stage B: pc weights (pre-split)
        for (int i = tid; i < 128 * 16; i += 512) {
            const int row = i >> 4, ch = i & 15;
            *(uint4*)(dsm + B_HI + 2 * (row * SRA + ch * 8)) =
                *(const uint4*)&g_pwh[(size_t)(kc * 128 + row) * NPC + nh * 128 + ch * 8];
            *(uint4*)(dsm + B_LO + 2 * (row * SRA + ch * 8)) =
                *(const uint4*)&g_pwl[(size_t)(kc * 128 + row) * NPC + nh * 128 + ch * 8];
        }
        if (nh == 0) {
            for (int i = tid; i < 128 * 16; i += 512) {
                const int row = i >> 4, c = i & 15;
                *(__nv_bfloat16*)(dsm + P_HHI + 2 * (row * SHD + c)) =
                    g_hdh[(kc * 128 + row) * 16 + c];
                *(__nv_bfloat16*)(dsm + P_HLO + 2 * (row * SHD + c)) =
                    g_hdl[(kc * 128 + row) * 16 + c];
            }
        }
        __syncthreads();

        // pc MMA
#pragma unroll
        for (int k8 = 0; k8 < 8; k8++) {
            const int k = k8 * 16;
            uint32_t ah[2][4], al[2][4];
#pragma unroll
            for (int mt = 0; mt < 2; mt++) {
                const uint32_t aoff = 2 * ((wm * 32 + mt * 16 + lr) * SRA + k + lc8);
                ldsm_x4(ah[mt][0], ah[mt][1], ah[mt][2], ah[mt][3], base_u + A_HI + aoff);
                ldsm_x4(al[mt][0], al[mt][1], al[mt][2], al[mt][3], base_u + A_LO + aoff);
            }
            uint32_t bh[4][2], bl[4][2];
#pragma unroll
            for (int p = 0; p < 2; p++) {
                const uint32_t boff = 2 * ((k + lr) * SRA + wn * 32 + p * 16 + lc8);
                ldsm_x4_t(bh[2*p][0], bh[2*p][1], bh[2*p+1][0], bh[2*p+1][1],
                          base_u + B_HI + boff);
                ldsm_x4_t(bl[2*p][0], bl[2*p][1], bl[2*p+1][0], bl[2*p+1][1],
                          base_u + B_LO + boff);
            }
#pragma unroll
            for (int mt = 0; mt < 2; mt++)
#pragma unroll
                for (int nt = 0; nt < 4; nt++) {
                    mma16816(acc[mt][nt], ah[mt], bh[nt]);
                    mma16816(acc[mt][nt], ah[mt], bl[nt]);
                    mma16816(acc[mt][nt], al[mt], bh[nt]);
                }
        }

        // hd MMA (warps 0-7 cover rows wid*16..+16)
        if (do_hd) {
#pragma unroll
            for (int k8 = 0; k8 < 8; k8++) {
                const int k = k8 * 16;
                uint32_t ah[4], al[4];
                const uint32_t aoff = 2 * ((wid * 16 + lr) * SRA + k + lc8);
                ldsm_x4(ah[0], ah[1], ah[2], ah[3], base_u + A_HI + aoff);
                ldsm_x4(al[0], al[1], al[2], al[3], base_u + A_LO + aoff);
                uint32_t bh[2][2], bl[2][2];
                const uint32_t boff = 2 * ((k + lr) * SHD + lc8);
                ldsm_x4_t(bh[0][0], bh[0][1], bh[1][0], bh[1][1], base_u + P_HHI + boff);
                ldsm_x4_t(bl[0][0], bl[0][1], bl[1][0], bl[1][1], base_u + P_HLO + boff);
#pragma unroll
                for (int nt = 0; nt < 2; nt++) {
                    mma16816(hacc[nt], ah, bh[nt]);
                    mma16816(hacc[nt], ah, bl[nt]);
                    mma16816(hacc[nt], al, bh[nt]);
                }
            }
        }
    }

    // pc epilogue
#pragma unroll
    for (int mt = 0; mt < 2; mt++)
#pragma unroll
    for (int nt = 0; nt < 4; nt++) {
        const int row = m0 + wm * 32 + mt * 16 + g;
        const int col = nh * 128 + wn * 32 + nt * 8 + tg2;
        const float b0 = __ldg(&pc_b[col]), b1 = __ldg(&pc_b[col + 1]);
        const float* a4 = acc[mt][nt];
        *(float2*)&pc_out[(size_t)row * 256 + col] = make_float2(a4[0] + b0, a4[1] + b1);
        *(float2*)&pc_out[(size_t)(row + 8) * 256 + col] = make_float2(a4[2] + b0, a4[3] + b1);
    }

    // hd epilogue
    if (do_hd) {
#pragma unroll
        for (int nt = 0; nt < 2; nt++) {
            const int c0 = nt * 8 + tg2;
            const int rowA = m0 + wid * 16 + g, rowB = rowA + 8;
            if (c0 < 12) {
                const float b = __ldg(&hd_b[c0]);
                hd_out[(size_t)rowA * 12 + c0] = hacc[nt][0] + b;
                hd_out[(size_t)rowB * 12 + c0] = hacc[nt][2] + b;
            }
            if (c0 + 1 < 12) {
                const float b = __ldg(&hd_b[c0 + 1]);
                hd_out[(size_t)rowA * 12 + c0 + 1] = hacc[nt][1] + b;
                hd_out[(size_t)rowB * 12 + c0 + 1] = hacc[nt][3] + b;
            }
        }
    }
}

// ---------------------------------------------------------------------------
extern "C" void kernel_launch(void* const* d_in, const int* in_sizes, int n_in,
                              void* d_out, int out_size)
{
    const float* x       = (const float*)d_in[0];
    const float* init    = (const float*)d_in[1];
    const float* rnn_w   = (const float*)d_in[2];
    const float* rnn_b   = (const float*)d_in[3];
    const float* state_w = (const float*)d_in[4];
    const float* state_b = (const float*)d_in[5];
    const float* cell_w  = (const float*)d_in[6];
    const float* cell_b  = (const float*)d_in[7];
    const float* bneck_w = (const float*)d_in[8];
    const float* pc_w    = (const float*)d_in[9];
    const float* pc_b    = (const float*)d_in[10];
    const float* hd_w    = (const float*)d_in[11];
    const float* hd_b    = (const float*)d_in[12];

    float* out = (float*)d_out;
    float* hd_out = out;
    float* pc_out = hd_out + (size_t)TB * NHDC;
    float* bn_out = pc_out + (size_t)TB * NPC;
    float* hs_out = bn_out + (size_t)TB * NBOT;
    float* cs_out = hs_out + (size_t)TB * NHD;

    float* c0p = nullptr;
    cudaGetSymbolAddress((void**)&c0p, g_c0);
    __nv_bfloat16 *hhp = nullptr, *hlp = nullptr;
    cudaGetSymbolAddress((void**)&hhp, g_hh);
    cudaGetSymbolAddress((void**)&hlp, g_hl);
    float* h0tmp = bn_out;   // scratch; overwritten by bn_kernel later

    cudaFuncSetAttribute(lstm_kernel, cudaFuncAttributeMaxDynamicSharedMemorySize, LSTM_SMEM);
    cudaFuncSetAttribute(bn_kernel, cudaFuncAttributeMaxDynamicSharedMemorySize, MM_SMEM);
    cudaFuncSetAttribute(pc_kernel, cudaFuncAttributeMaxDynamicSharedMemorySize, PC_SMEM);

    gemm_kernel<<<dim3(2, 16), 256>>>(init, state_w, state_b, h0tmp, hhp, hlp, BB, NHD, NIC);
    gemm_kernel<<<dim3(2, 16), 256>>>(init, cell_w, cell_b, c0p, nullptr, nullptr, BB, NHD, NIC);
    split_w_kernel<<<(NHD * NBOT + NBOT * NPC + NBOT * 16 + 255) / 256, 256>>>(
        bneck_w, pc_w, hd_w);

    lstm_kernel<<<128, 512, LSTM_SMEM>>>(x, rnn_w, rnn_b, hs_out, cs_out);

    bn_kernel<<<dim3(TB / 128, 2), 512, MM_SMEM>>>(bn_out);
    pc_kernel<<<dim3(TB / 128, 2), 512, PC_SMEM>>>(bn_out, pc_b, hd_b, pc_out, hd_out);
}

// round 9
// speedup vs baseline: 2.3715x; 1.1002x over previous
#include <cuda_runtime.h>
#include <cuda_bf16.h>
#include <cstdint>
#include <cstddef>

#define TT   100
#define BB   1024
#define NHD  128
#define NGATE 512
#define NIC  268
#define NBOT 256
#define NPC  256
#define NHDC 12
#define TB   (TT * BB)

// ---------------------------------------------------------------------------
// device scratch
// ---------------------------------------------------------------------------
__device__ float g_c0[BB * NHD];
// h history pre-split bf16: slot 0 = h0, slot t+1 = h_t
__device__ __nv_bfloat16 g_hh[(size_t)(TT + 1) * BB * NHD];
__device__ __nv_bfloat16 g_hl[(size_t)(TT + 1) * BB * NHD];
__device__ __nv_bfloat16 g_bwh[NHD * NBOT], g_bwl[NHD * NBOT];
__device__ __nv_bfloat16 g_pwh[NBOT * NPC], g_pwl[NBOT * NPC];
__device__ __nv_bfloat16 g_hdh[NBOT * 16], g_hdl[NBOT * 16];
// per-32-row-tile flags: g_flag[rtf*32 + cg], monotone epochs across replays
__device__ unsigned g_flag[32 * 32];

__device__ __forceinline__ float sigm(float v) { return 1.0f / (1.0f + __expf(-v)); }
__device__ __forceinline__ float tanh_fast(float v) {
    return 1.0f - 2.0f / (__expf(2.0f * v) + 1.0f);
}
__device__ __forceinline__ void split2(float v, __nv_bfloat16& hi, __nv_bfloat16& lo) {
    hi = __float2bfloat16(v);
    lo = __float2bfloat16(v - __bfloat162float(hi));
}
__device__ __forceinline__ uint32_t smem_u32(const void* p) {
    uint32_t a;
    asm("{ .reg .u64 t; cvta.to.shared.u64 t, %1; cvt.u32.u64 %0, t; }" : "=r"(a) : "l"(p));
    return a;
}
__device__ __forceinline__ unsigned ld_acq(const unsigned* p) {
    unsigned v;
    asm volatile("ld.acquire.gpu.global.u32 %0, [%1];" : "=r"(v) : "l"(p) : "memory");
    return v;
}
__device__ __forceinline__ void st_rel(unsigned* p, unsigned v) {
    asm volatile("st.release.gpu.global.u32 [%0], %1;" :: "l"(p), "r"(v) : "memory");
}
__device__ __forceinline__ void ldsm_x4(uint32_t& r0, uint32_t& r1, uint32_t& r2,
                                        uint32_t& r3, uint32_t addr) {
    asm volatile("ldmatrix.sync.aligned.m8n8.x4.shared.b16 {%0,%1,%2,%3}, [%4];"
                 : "=r"(r0), "=r"(r1), "=r"(r2), "=r"(r3) : "r"(addr));
}
__device__ __forceinline__ void ldsm_x4_t(uint32_t& r0, uint32_t& r1, uint32_t& r2,
                                          uint32_t& r3, uint32_t addr) {
    asm volatile("ldmatrix.sync.aligned.m8n8.x4.trans.shared.b16 {%0,%1,%2,%3}, [%4];"
                 : "=r"(r0), "=r"(r1), "=r"(r2), "=r"(r3) : "r"(addr));
}
__device__ __forceinline__ void ldsm_x2_t(uint32_t& r0, uint32_t& r1, uint32_t addr) {
    asm volatile("ldmatrix.sync.aligned.m8n8.x2.trans.shared.b16 {%0,%1}, [%2];"
                 : "=r"(r0), "=r"(r1) : "r"(addr));
}
__device__ __forceinline__ void mma16816(float* d, const uint32_t* a, const uint32_t* b) {
    asm volatile(
        "mma.sync.aligned.m16n8k16.row.col.f32.bf16.bf16.f32 "
        "{%0,%1,%2,%3}, {%4,%5,%6,%7}, {%8,%9}, {%0,%1,%2,%3};"
        : "+f"(d[0]), "+f"(d[1]), "+f"(d[2]), "+f"(d[3])
        : "r"(a[0]), "r"(a[1]), "r"(a[2]), "r"(a[3]), "r"(b[0]), "r"(b[1]));
}
__device__ __forceinline__ void bar_grp(int wg) {
    if (wg == 0) asm volatile("bar.sync 1, 256;" ::: "memory");
    else         asm volatile("bar.sync 2, 256;" ::: "memory");
}

// ---------------------------------------------------------------------------
// weight pre-split (bneck_w, pc_w, hd_w padded to N16)
// ---------------------------------------------------------------------------
__global__ void split_w_kernel(const float* __restrict__ bw, const float* __restrict__ pw,
                               const float* __restrict__ hw)
{
    const int i = blockIdx.x * 256 + threadIdx.x;
    __nv_bfloat16 hi, lo;
    if (i < NHD * NBOT) {
        split2(bw[i], hi, lo);
        g_bwh[i] = hi; g_bwl[i] = lo;
    } else if (i < NHD * NBOT + NBOT * NPC) {
        const int j = i - NHD * NBOT;
        split2(pw[j], hi, lo);
        g_pwh[j] = hi; g_pwl[j] = lo;
    } else if (i < NHD * NBOT + NBOT * NPC + NBOT * 16) {
        const int j = i - NHD * NBOT - NBOT * NPC;
        const int k = j >> 4, n = j & 15;
        split2((n < 12) ? hw[k * 12 + n] : 0.0f, hi, lo);
        g_hdh[j] = hi; g_hdl[j] = lo;
    }
}

// ---------------------------------------------------------------------------
// fp32 GEMM for h0/c0 init; optional bf16 hi/lo emission (h0 -> slot 0)
// ---------------------------------------------------------------------------
__global__ void gemm_kernel(const float* __restrict__ A, const float* __restrict__ W,
                            const float* __restrict__ bias, float* __restrict__ C,
                            __nv_bfloat16* __restrict__ oh, __nv_bfloat16* __restrict__ ol,
                            int M, int N, int K)
{
    __shared__ float As[16][68];
    __shared__ float Ws[16][68];
    const int tid = threadIdx.x;
    const int tx = tid & 15, ty = tid >> 4;
    const int n0 = blockIdx.x * 64, m0 = blockIdx.y * 64;

    float acc[4][4];
#pragma unroll
    for (int r = 0; r < 4; r++)
#pragma unroll
        for (int q = 0; q < 4; q++) acc[r][q] = 0.0f;

    for (int k0 = 0; k0 < K; k0 += 16) {
        {
            const int k = tid & 15, m = tid >> 4;
#pragma unroll
            for (int p = 0; p < 4; p++) {
                const int mm = m + p * 16;
                float v = 0.0f;
                if (k0 + k < K) v = A[(size_t)(m0 + mm) * K + (k0 + k)];
                As[k][mm] = v;
            }
        }
        {
            const int n = tid & 63, kb = tid >> 6;
#pragma unroll
            for (int p = 0; p < 4; p++) {
                const int kk = kb + p * 4;
                float v = 0.0f;
                if ((k0 + kk < K) && (n0 + n < N)) v = W[(size_t)(k0 + kk) * N + (n0 + n)];
                Ws[kk][n] = v;
            }
        }
        __syncthreads();
#pragma unroll
        for (int kk = 0; kk < 16; kk++) {
            const float4 a4 = *(const float4*)&As[kk][ty * 4];
            const float4 b4 = *(const float4*)&Ws[kk][tx * 4];
            const float av[4] = {a4.x, a4.y, a4.z, a4.w};
            const float bv[4] = {b4.x, b4.y, b4.z, b4.w};
#pragma unroll
            for (int r = 0; r < 4; r++)
#pragma unroll
                for (int q = 0; q < 4; q++)
                    acc[r][q] = fmaf(av[r], bv[q], acc[r][q]);
        }
        __syncthreads();
    }
#pragma unroll
    for (int r = 0; r < 4; r++) {
        const int m = m0 + ty * 4 + r;
#pragma unroll
        for (int q = 0; q < 4; q++) {
            const int n = n0 + tx * 4 + q;
            if (n < N) {
                const float v = acc[r][q] + (bias ? bias[n] : 0.0f);
                C[(size_t)m * N + n] = v;
                if (oh) {
                    __nv_bfloat16 hi, lo;
                    split2(v, hi, lo);
                    oh[(size_t)m * N + n] = hi;
                    ol[(size_t)m * N + n] = lo;
                }
            }
        }
    }
}

// ---------------------------------------------------------------------------
// LSTM recurrence + fused bn GEMM.
// 128 blocks x 512 threads = two warp-groups (32 rows each) x 8 unit-groups.
// Sync: per-32-row-tile flags, single-thread release store / acquire polls.
// bn: at step t (>=1) the staged A tile is h slot t (an hs row block) —
// compute bn cols [cg*32,+32) reusing the A fragments; tail step t==TT
// handles the last slot.
// ---------------------------------------------------------------------------
#define L_WHH 0u                            // [128][72] bf16
#define L_WHL 18432u
#define L_A(g)   (36864u + (g) * 17408u)    // hi [32][136] bf16; lo at +8704
#define L_BNW_HI 71680u                     // [128][40] bf16
#define L_BNW_LO 81920u
#define L_XS(g)  (92160u + (g) * 512u)      // [32][4] f32
#define L_WX  93184u                        // [3][64] f32
#define L_BS  93952u                        // [64] f32
#define L_HST(g) (94208u + (g) * 5120u)     // [32][20] f32; cst +2560
#define LSTM_SMEM 104448u
#define SWH 72
#define SAH 136
#define SBN 40
#define SHT 20

__global__ void __launch_bounds__(512, 1)
lstm_kernel(const float* __restrict__ x, const float* __restrict__ rnn_w,
            const float* __restrict__ rnn_b,
            float* __restrict__ hs, float* __restrict__ cs,
            float* __restrict__ bn_out)
{
    extern __shared__ __align__(16) char dsm[];
    const uint32_t base_u = smem_u32(dsm);
    __shared__ unsigned s_base[2];

    const int tid  = threadIdx.x;
    const int wg   = tid >> 8;          // warpgroup 0/1
    const int wtid = tid & 255;
    const int gw   = wtid >> 5;         // warp in group 0..7
    const int lane = tid & 31;
    const int wm   = gw & 1,  wn = gw >> 1;   // gates: 2 row-halves x 4 col-grps
    const int bwn  = gw >> 1;                 // bn: 4 col-grps of 8
    const int g    = lane >> 2, tg = lane & 3;
    const int lr   = lane & 15, lc8 = (lane >> 4) << 3;
    const int cg   = blockIdx.x & 7;
    const int rp   = blockIdx.x >> 3;
    const int hu0  = cg * 16;
    const int r0g  = rp * 64 + wg * 32;
    const int rtf  = rp * 2 + wg;

    float* xs  = (float*)(dsm + L_XS(wg));
    float* wx  = (float*)(dsm + L_WX);
    float* bs  = (float*)(dsm + L_BS);
    float* hst = (float*)(dsm + L_HST(wg));
    float* cst = (float*)(dsm + L_HST(wg) + 2560u);
    const uint32_t AHI = L_A(wg), ALO = AHI + 8704u;

    // stage gate weights once (cols c = u*4+q), bf16 hi/lo
    for (int i = tid; i < 128 * 64; i += 512) {
        const int k = i >> 6, c = i & 63;
        const int u = c >> 2, q = c & 3;
        __nv_bfloat16 hi, lo;
        split2(rnn_w[(size_t)(3 + k) * NGATE + q * NHD + hu0 + u], hi, lo);
        *(__nv_bfloat16*)(dsm + L_WHH + 2 * (k * SWH + c)) = hi;
        *(__nv_bfloat16*)(dsm + L_WHL + 2 * (k * SWH + c)) = lo;
    }
    // stage bn weight chunk [128][cg*32..+32] (pre-split)
    {
        const int i = tid;  // 512 = 128 rows x 4 uint4
        const int k = i >> 2, c4 = i & 3;
        *(uint4*)(dsm + L_BNW_HI + 2 * (k * SBN) + c4 * 16) =
            *(const uint4*)&g_bwh[(size_t)k * NBOT + cg * 32 + c4 * 8];
        *(uint4*)(dsm + L_BNW_LO + 2 * (k * SBN) + c4 * 16) =
            *(const uint4*)&g_bwl[(size_t)k * NBOT + cg * 32 + c4 * 8];
    }
    if (tid < 192) {
        const int m = tid >> 6, c = tid & 63;
        const int u = c >> 2, q = c & 3;
        wx[m * 64 + c] = rnn_w[(size_t)m * NGATE + q * NHD + hu0 + u];
    }
    if (tid < 64) {
        const int u = tid >> 2, q = tid & 3;
        bs[tid] = rnn_b[q * NHD + hu0 + u];
    }
    if (wtid == 0) s_base[wg] = ld_acq(&g_flag[rtf * 32 + cg]);

    // persistent cell state (even-tg lanes)
    const int rA = wm * 16 + g, rB = rA + 8;
    float creg[4];
    if (!(tg & 1)) {
#pragma unroll
        for (int nt = 0; nt < 2; nt++) {
            const int ul = (wn * 16 + nt * 8 + tg * 2) >> 2;
            creg[nt * 2]     = g_c0[(size_t)(r0g + rA) * NHD + hu0 + ul];
            creg[nt * 2 + 1] = g_c0[(size_t)(r0g + rB) * NHD + hu0 + ul];
        }
    }
    __syncthreads();
    const unsigned base = s_base[wg];

    for (int t = 0; t <= TT; t++) {
        // wait for the 7 peer blocks (epoch-relative, acquire loads)
        if (gw == 0) {
            if (t > 0 && lane < 8 && lane != cg) {
                const unsigned tgt = base + (unsigned)t;
                while (ld_acq(&g_flag[rtf * 32 + lane]) < tgt) { }
            }
            __syncwarp();
        }
        bar_grp(wg);

        // stage A = h slot t (pre-split) + x_t
        {
            const size_t sb = ((size_t)t * BB + r0g) * NHD;
            for (int i = wtid; i < 32 * 16; i += 256) {
                const int row = i >> 4, ch = i & 15;
                *(uint4*)(dsm + AHI + 2 * (row * SAH + ch * 8)) =
                    *(const uint4*)&g_hh[sb + (size_t)row * NHD + ch * 8];
                *(uint4*)(dsm + ALO + 2 * (row * SAH + ch * 8)) =
                    *(const uint4*)&g_hl[sb + (size_t)row * NHD + ch * 8];
            }
            if (t < TT && wtid < 96)
                xs[(wtid / 3) * 4 + (wtid % 3)] = x[((size_t)t * BB + r0g) * 3 + wtid];
        }
        bar_grp(wg);

        float bnacc[4] = {0.0f, 0.0f, 0.0f, 0.0f};

        if (t < TT) {
            // gate MMA (4-term split, exact) + fused bn MMA (3-term)
            float acc[2][4];
#pragma unroll
            for (int a = 0; a < 2; a++)
#pragma unroll
                for (int b = 0; b < 4; b++) acc[a][b] = 0.0f;

#pragma unroll
            for (int kc = 0; kc < 8; kc++) {
                const int k = kc * 16;
                uint32_t ah[4], al[4];
                const uint32_t aoff = 2 * ((wm * 16 + lr) * SAH + k + lc8);
                ldsm_x4(ah[0], ah[1], ah[2], ah[3], base_u + AHI + aoff);
                ldsm_x4(al[0], al[1], al[2], al[3], base_u + ALO + aoff);
                uint32_t bh[2][2], bl[2][2];
                const uint32_t boff = 2 * ((k + lr) * SWH + wn * 16 + lc8);
                ldsm_x4_t(bh[0][0], bh[0][1], bh[1][0], bh[1][1], base_u + L_WHH + boff);
                ldsm_x4_t(bl[0][0], bl[0][1], bl[1][0], bl[1][1], base_u + L_WHL + boff);
#pragma unroll
                for (int nt = 0; nt < 2; nt++) {
                    mma16816(acc[nt], ah, bh[nt]);
                    mma16816(acc[nt], ah, bl[nt]);
                    mma16816(acc[nt], al, bh[nt]);
                    mma16816(acc[nt], al, bl[nt]);
                }
                // bn (cols cg*32 + bwn*8 .. +8)
                uint32_t nbh[2], nbl[2];
                const uint32_t nboff = 2 * ((k + lr) * SBN + bwn * 8);
                ldsm_x2_t(nbh[0], nbh[1], base_u + L_BNW_HI + nboff);
                ldsm_x2_t(nbl[0], nbl[1], base_u + L_BNW_LO + nboff);
                mma16816(bnacc, ah, nbh);
                mma16816(bnacc, ah, nbl);
                mma16816(bnacc, al, nbh);
            }

            // bn store (A tile = hs row block t-1) — skip t==0 (h0 isn't an hs row)
            if (t >= 1) {
                const size_t row = (size_t)(t - 1) * BB + r0g + wm * 16 + g;
                const int col = cg * 32 + bwn * 8 + tg * 2;
                *(float2*)&bn_out[row * 256 + col] = make_float2(bnacc[0], bnacc[1]);
                *(float2*)&bn_out[(row + 8) * 256 + col] = make_float2(bnacc[2], bnacc[3]);
            }

            // bias + x contribution (fp32 exact)
            const float xa0 = xs[rA * 4], xa1 = xs[rA * 4 + 1], xa2 = xs[rA * 4 + 2];
            const float xb0 = xs[rB * 4], xb1 = xs[rB * 4 + 1], xb2 = xs[rB * 4 + 2];
#pragma unroll
            for (int nt = 0; nt < 2; nt++) {
                const int c0 = wn * 16 + nt * 8 + tg * 2;
#pragma unroll
                for (int cc = 0; cc < 2; cc++) {
                    const int c = c0 + cc;
                    const float w0 = wx[c], w1 = wx[64 + c], w2 = wx[128 + c], bb = bs[c];
                    acc[nt][cc]     += bb + xa0 * w0 + xa1 * w1 + xa2 * w2;
                    acc[nt][2 + cc] += bb + xb0 * w0 + xb1 * w1 + xb2 * w2;
                }
            }

            // gate exchange + cell update
#pragma unroll
            for (int nt = 0; nt < 2; nt++) {
                const float p0 = __shfl_xor_sync(0xffffffffu, acc[nt][0], 1);
                const float p1 = __shfl_xor_sync(0xffffffffu, acc[nt][1], 1);
                const float p2 = __shfl_xor_sync(0xffffffffu, acc[nt][2], 1);
                const float p3 = __shfl_xor_sync(0xffffffffu, acc[nt][3], 1);
                if (!(tg & 1)) {
                    const int ul = (wn * 16 + nt * 8 + tg * 2) >> 2;
                    const float cA = creg[nt * 2] * sigm(p0 + 1.0f)
                                   + sigm(acc[nt][0]) * tanh_fast(acc[nt][1]);
                    const float hA = tanh_fast(cA) * sigm(p1);
                    const float cB = creg[nt * 2 + 1] * sigm(p2 + 1.0f)
                                   + sigm(acc[nt][2]) * tanh_fast(acc[nt][3]);
                    const float hB = tanh_fast(cB) * sigm(p3);
                    creg[nt * 2] = cA;
                    creg[nt * 2 + 1] = cB;
                    hst[rA * SHT + ul] = hA;
                    cst[rA * SHT + ul] = cA;
                    hst[rB * SHT + ul] = hB;
                    cst[rB * SHT + ul] = cB;
                }
            }
            bar_grp(wg);

            // publish h slot t+1 (bf16 split) — weak stores, then release flag
            if (wtid < 128) {
                const int row = wtid >> 2, q4 = wtid & 3;
                const float4 hv = *(const float4*)&hst[row * SHT + q4 * 4];
                __nv_bfloat16 h0b, l0b, h1b, l1b, h2b, l2b, h3b, l3b;
                split2(hv.x, h0b, l0b); split2(hv.y, h1b, l1b);
                split2(hv.z, h2b, l2b); split2(hv.w, h3b, l3b);
                const size_t gb = ((size_t)(t + 1) * BB + r0g + row) * NHD + hu0 + q4 * 4;
                __nv_bfloat162 p0; p0.x = h0b; p0.y = h1b;
                __nv_bfloat162 p1; p1.x = h2b; p1.y = h3b;
                __nv_bfloat162 q0; q0.x = l0b; q0.y = l1b;
                __nv_bfloat162 q1; q1.x = l2b; q1.y = l3b;
                *(__nv_bfloat162*)&g_hh[gb]     = p0;
                *(__nv_bfloat162*)&g_hh[gb + 2] = p1;
                *(__nv_bfloat162*)&g_hl[gb]     = q0;
                *(__nv_bfloat162*)&g_hl[gb + 2] = q1;
            }
            bar_grp(wg);
            if (wtid == 0)
                st_rel(&g_flag[rtf * 32 + cg], base + (unsigned)t + 1u);

            // fp32 hs/cs outputs — off the sync critical path
            if (wtid < 128) {
                const int row = wtid >> 2, q4 = wtid & 3;
                const float4 hv = *(const float4*)&hst[row * SHT + q4 * 4];
                const float4 cv = *(const float4*)&cst[row * SHT + q4 * 4];
                const size_t go = ((size_t)t * BB + r0g + row) * NHD + hu0 + q4 * 4;
                *(float4*)&hs[go] = hv;
                *(float4*)&cs[go] = cv;
            }
        } else {
            // tail: bn for the last hs row block (slot TT)
#pragma unroll
            for (int kc = 0; kc < 8; kc++) {
                const int k = kc * 16;
                uint32_t ah[4], al[4];
                const uint32_t aoff = 2 * ((wm * 16 + lr) * SAH + k + lc8);
                ldsm_x4(ah[0], ah[1], ah[2], ah[3], base_u + AHI + aoff);
                ldsm_x4(al[0], al[1], al[2], al[3], base_u + ALO + aoff);
                uint32_t nbh[2], nbl[2];
                const uint32_t nboff = 2 * ((k + lr) * SBN + bwn * 8);
                ldsm_x2_t(nbh[0], nbh[1], base_u + L_BNW_HI + nboff);
                ldsm_x2_t(nbl[0], nbl[1], base_u + L_BNW_LO + nboff);
                mma16816(bnacc, ah, nbh);
                mma16816(bnacc, ah, nbl);
                mma16816(bnacc, al, nbh);
            }
            const size_t row = (size_t)(TT - 1) * BB + r0g + wm * 16 + g;
            const int col = cg * 32 + bwn * 8 + tg * 2;
            *(float2*)&bn_out[row * 256 + col] = make_float2(bnacc[0], bnacc[1]);
            *(float2*)&bn_out[(row + 8) * 256 + col] = make_float2(bnacc[2], bnacc[3]);
        }
    }
}

// ---------------------------------------------------------------------------
// pc = bn @ pc_w + pc_b  (A split inline from bn fp32) with fused
// hd = bn @ hd_w + hd_b  (HMMA N=16 padded, warps 0-7 on nh==0 blocks)
// ---------------------------------------------------------------------------
#define SRA  136
#define A_HI 0u
#define A_LO 34816u
#define B_HI 69632u
#define B_LO 104448u
#define P_HHI 139264u
#define P_HLO 145408u
#define PC_SMEM 151552u
#define SHD 24

__global__ void __launch_bounds__(512, 1)
pc_kernel(const float* __restrict__ bn, const float* __restrict__ pc_b,
          const float* __restrict__ hd_b,
          float* __restrict__ pc_out, float* __restrict__ hd_out)
{
    extern __shared__ __align__(16) char dsm[];
    const uint32_t base_u = smem_u32(dsm);
    const int tid = threadIdx.x;
    const int wid = tid >> 5, lane = tid & 31;
    const int wm = wid & 3, wn = wid >> 2;
    const int g = lane >> 2, tg2 = (lane & 3) * 2;
    const int lr = lane & 15, lc8 = (lane >> 4) << 3;
    const int m0 = blockIdx.x * 128, nh = blockIdx.y;
    const bool do_hd = (nh == 0) && (wid < 8);

    float acc[2][4][4];
#pragma unroll
    for (int a = 0; a < 2; a++)
#pragma unroll
        for (int b = 0; b < 4; b++)
#pragma unroll
            for (int c = 0; c < 4; c++) acc[a][b][c] = 0.0f;
    float hacc[2][4];
#pragma unroll
    for (int a = 0; a < 2; a++)
#pragma unroll
        for (int b = 0; b < 4; b++) hacc[a][b] = 0.0f;

#pragma unroll 1
    for (int kc = 0; kc < 2; kc++) {
        __syncthreads();
        for (int i = tid; i < 128 * 128; i += 512) {
            const int row = i >> 7, k = i & 127;
            __nv_bfloat16 hi, lo;
            split2(bn[(size_t)(m0 + row) * 256 + kc * 128 + k], hi, lo);
            *(__nv_bfloat16*)(dsm + A_HI + 2 * (row * SRA + k)) = hi;
            *(__nv_bfloat16*)(dsm + A_LO + 2 * (row * SRA + k)) = lo;
        }
        for (int i = tid; i < 128 * 16; i += 512) {
            const int row = i >> 4, ch = i & 15;
            *(uint4*)(dsm + B_HI + 2 * (row * SRA + ch * 8)) =
                *(const uint4*)&g_pwh[(size_t)(kc * 128 + row) * NPC + nh * 128 + ch * 8];
            *(uint4*)(dsm + B_LO + 2 * (row * SRA + ch * 8)) =
                *(const uint4*)&g_pwl[(size_t)(kc * 128 + row) * NPC + nh * 128 + ch * 8];
        }
        if (nh == 0) {
            for (int i = tid; i < 128 * 16; i += 512) {
                const int row = i >> 4, c = i & 15;
                *(__nv_bfloat16*)(dsm + P_HHI + 2 * (row * SHD + c)) =
                    g_hdh[(kc * 128 + row) * 16 + c];
                *(__nv_bfloat16*)(dsm + P_HLO + 2 * (row * SHD + c)) =
                    g_hdl[(kc * 128 + row) * 16 + c];
            }
        }
        __syncthreads();

#pragma unroll
        for (int k8 = 0; k8 < 8; k8++) {
            const int k = k8 * 16;
            uint32_t ah[2][4], al[2][4];
#pragma unroll
            for (int mt = 0; mt < 2; mt++) {
                const uint32_t aoff = 2 * ((wm * 32 + mt * 16 + lr) * SRA + k + lc8);
                ldsm_x4(ah[mt][0], ah[mt][1], ah[mt][2], ah[mt][3], base_u + A_HI + aoff);
                ldsm_x4(al[mt][0], al[mt][1], al[mt][2], al[mt][3], base_u + A_LO + aoff);
            }
            uint32_t bh[4][2], bl[4][2];
#pragma unroll
            for (int p = 0; p < 2; p++) {
                const uint32_t boff = 2 * ((k + lr) * SRA + wn * 32 + p * 16 + lc8);
                ldsm_x4_t(bh[2*p][0], bh[2*p][1], bh[2*p+1][0], bh[2*p+1][1],
                          base_u + B_HI + boff);
                ldsm_x4_t(bl[2*p][0], bl[2*p][1], bl[2*p+1][0], bl[2*p+1][1],
                          base_u + B_LO + boff);
            }
#pragma unroll
            for (int mt = 0; mt < 2; mt++)
#pragma unroll
                for (int nt = 0; nt < 4; nt++) {
                    mma16816(acc[mt][nt], ah[mt], bh[nt]);
                    mma16816(acc[mt][nt], ah[mt], bl[nt]);
                    mma16816(acc[mt][nt], al[mt], bh[nt]);
                }
        }

        if (do_hd) {
#pragma unroll
            for (int k8 = 0; k8 < 8; k8++) {
                const int k = k8 * 16;
                uint32_t ah[4], al[4];
                const uint32_t aoff = 2 * ((wid * 16 + lr) * SRA + k + lc8);
                ldsm_x4(ah[0], ah[1], ah[2], ah[3], base_u + A_HI + aoff);
                ldsm_x4(al[0], al[1], al[2], al[3], base_u + A_LO + aoff);
                uint32_t bh[2][2], bl[2][2];
                const uint32_t boff = 2 * ((k + lr) * SHD + lc8);
                ldsm_x4_t(bh[0][0], bh[0][1], bh[1][0], bh[1][1], base_u + P_HHI + boff);
                ldsm_x4_t(bl[0][0], bl[0][1], bl[1][0], bl[1][1], base_u + P_HLO + boff);
#pragma unroll
                for (int nt = 0; nt < 2; nt++) {
                    mma16816(hacc[nt], ah, bh[nt]);
                    mma16816(hacc[nt], ah, bl[nt]);
                    mma16816(hacc[nt], al, bh[nt]);
                }
            }
        }
    }

#pragma unroll
    for (int mt = 0; mt < 2; mt++)
#pragma unroll
    for (int nt = 0; nt < 4; nt++) {
        const int row = m0 + wm * 32 + mt * 16 + g;
        const int col = nh * 128 + wn * 32 + nt * 8 + tg2;
        const float b0 = __ldg(&pc_b[col]), b1 = __ldg(&pc_b[col + 1]);
        const float* a4 = acc[mt][nt];
        *(float2*)&pc_out[(size_t)row * 256 + col] = make_float2(a4[0] + b0, a4[1] + b1);
        *(float2*)&pc_out[(size_t)(row + 8) * 256 + col] = make_float2(a4[2] + b0, a4[3] + b1);
    }

    if (do_hd) {
#pragma unroll
        for (int nt = 0; nt < 2; nt++) {
            const int c0 = nt * 8 + tg2;
            const int rowA = m0 + wid * 16 + g, rowB = rowA + 8;
            if (c0 < 12) {
                const float b = __ldg(&hd_b[c0]);
                hd_out[(size_t)rowA * 12 + c0] = hacc[nt][0] + b;
                hd_out[(size_t)rowB * 12 + c0] = hacc[nt][2] + b;
            }
            if (c0 + 1 < 12) {
                const float b = __ldg(&hd_b[c0 + 1]);
                hd_out[(size_t)rowA * 12 + c0 + 1] = hacc[nt][1] + b;
                hd_out[(size_t)rowB * 12 + c0 + 1] = hacc[nt][3] + b;
            }
        }
    }
}

// ---------------------------------------------------------------------------
extern "C" void kernel_launch(void* const* d_in, const int* in_sizes, int n_in,
                              void* d_out, int out_size)
{
    const float* x       = (const float*)d_in[0];
    const float* init    = (const float*)d_in[1];
    const float* rnn_w   = (const float*)d_in[2];
    const float* rnn_b   = (const float*)d_in[3];
    const float* state_w = (const float*)d_in[4];
    const float* state_b = (const float*)d_in[5];
    const float* cell_w  = (const float*)d_in[6];
    const float* cell_b  = (const float*)d_in[7];
    const float* bneck_w = (const float*)d_in[8];
    const float* pc_w    = (const float*)d_in[9];
    const float* pc_b    = (const float*)d_in[10];
    const float* hd_w    = (const float*)d_in[11];
    const float* hd_b    = (const float*)d_in[12];

    float* out = (float*)d_out;
    float* hd_out = out;
    float* pc_out = hd_out + (size_t)TB * NHDC;
    float* bn_out = pc_out + (size_t)TB * NPC;
    float* hs_out = bn_out + (size_t)TB * NBOT;
    float* cs_out = hs_out + (size_t)TB * NHD;

    float* c0p = nullptr;
    cudaGetSymbolAddress((void**)&c0p, g_c0);
    __nv_bfloat16 *hhp = nullptr, *hlp = nullptr;
    cudaGetSymbolAddress((void**)&hhp, g_hh);
    cudaGetSymbolAddress((void**)&hlp, g_hl);
    float* h0tmp = bn_out;   // scratch; fully overwritten by lstm_kernel's bn

    cudaFuncSetAttribute(lstm_kernel, cudaFuncAttributeMaxDynamicSharedMemorySize, LSTM_SMEM);
    cudaFuncSetAttribute(pc_kernel, cudaFuncAttributeMaxDynamicSharedMemorySize, PC_SMEM);

    gemm_kernel<<<dim3(2, 16), 256>>>(init, state_w, state_b, h0tmp, hhp, hlp, BB, NHD, NIC);
    gemm_kernel<<<dim3(2, 16), 256>>>(init, cell_w, cell_b, c0p, nullptr, nullptr, BB, NHD, NIC);
    split_w_kernel<<<(NHD * NBOT + NBOT * NPC + NBOT * 16 + 255) / 256, 256>>>(
        bneck_w, pc_w, hd_w);

    lstm_kernel<<<128, 512, LSTM_SMEM>>>(x, rnn_w, rnn_b, hs_out, cs_out, bn_out);

    pc_kernel<<<dim3(TB / 128, 2), 512, PC_SMEM>>>(bn_out, pc_b, hd_b, pc_out, hd_out);
}